// round 3
// baseline (speedup 1.0000x reference)
#include <cuda_runtime.h>
#include <math.h>

#define Bb   128
#define Tt   384
#define Cc   256
#define Hh   4
#define KVh  2
#define Dd   64
#define REPr 2

// ---------------- scratch (static device globals; no allocs) ----------------
__device__ float g_q[(size_t)Bb * Hh * Tt * Dd];   // [B,H,T,D]
__device__ float g_k[(size_t)Bb * KVh * Tt * Dd];  // [B,KV,T,D]
__device__ float g_v[(size_t)Bb * KVh * Tt * Dd];  // [B,KV,T,D]
__device__ float g_y[(size_t)Bb * Tt * Cc];        // [B,T,C] (C = h*D+d)

// ---------------- tiled fp32 GEMM: C[M,N] = A[M,K] @ W[K,N] -----------------
// NH>0: remap output to [B, NH, T, D] layout; NH==0: plain row-major out.
__global__ void gemm_kernel(const float* __restrict__ A,
                            const float* __restrict__ W,
                            float* __restrict__ out,
                            int M, int N, int K, int NH)
{
    __shared__ float As[64][17];
    __shared__ float Bs[16][64];

    int tid = threadIdx.x;              // 0..255
    int tx  = tid & 15;                 // 0..15  (N micro)
    int ty  = tid >> 4;                 // 0..15  (M micro)
    int m0  = blockIdx.y * 64;
    int n0  = blockIdx.x * 64;

    float acc[4][4];
    #pragma unroll
    for (int i = 0; i < 4; i++)
        #pragma unroll
        for (int j = 0; j < 4; j++) acc[i][j] = 0.f;

    for (int k0 = 0; k0 < K; k0 += 16) {
        // load A tile: 64x16 = 1024 floats, 4 consecutive per thread
        {
            int idx = tid * 4;
            int r = idx >> 4, c = idx & 15;
            float4 av = *(const float4*)(A + (size_t)(m0 + r) * K + k0 + c);
            As[r][c + 0] = av.x; As[r][c + 1] = av.y;
            As[r][c + 2] = av.z; As[r][c + 3] = av.w;
        }
        // load W tile: 16x64 = 1024 floats
        {
            int idx = tid * 4;
            int r = idx >> 6, c = idx & 63;
            *(float4*)(&Bs[r][c]) = *(const float4*)(W + (size_t)(k0 + r) * N + n0 + c);
        }
        __syncthreads();

        #pragma unroll
        for (int kk = 0; kk < 16; kk++) {
            float a0 = As[ty * 4 + 0][kk];
            float a1 = As[ty * 4 + 1][kk];
            float a2 = As[ty * 4 + 2][kk];
            float a3 = As[ty * 4 + 3][kk];
            float4 b = *(float4*)(&Bs[kk][tx * 4]);
            acc[0][0] += a0 * b.x; acc[0][1] += a0 * b.y; acc[0][2] += a0 * b.z; acc[0][3] += a0 * b.w;
            acc[1][0] += a1 * b.x; acc[1][1] += a1 * b.y; acc[1][2] += a1 * b.z; acc[1][3] += a1 * b.w;
            acc[2][0] += a2 * b.x; acc[2][1] += a2 * b.y; acc[2][2] += a2 * b.z; acc[2][3] += a2 * b.w;
            acc[3][0] += a3 * b.x; acc[3][1] += a3 * b.y; acc[3][2] += a3 * b.z; acc[3][3] += a3 * b.w;
        }
        __syncthreads();
    }

    #pragma unroll
    for (int i = 0; i < 4; i++) {
        int m = m0 + ty * 4 + i;
        #pragma unroll
        for (int j = 0; j < 4; j++) {
            int n = n0 + tx * 4 + j;
            if (NH > 0) {
                int b = m / Tt, t = m % Tt;
                int h = n / Dd, d = n % Dd;
                out[(((size_t)b * NH + h) * Tt + t) * Dd + d] = acc[i][j];
            } else {
                out[(size_t)m * N + n] = acc[i][j];
            }
        }
    }
}

// ---------------- RoPE over q [B,H,T,D] and k [B,KV,T,D] --------------------
__global__ void rope_kernel(float* __restrict__ q, float* __restrict__ k)
{
    int tid = threadIdx.x;                       // 0..255
    int row = blockIdx.x * 8 + (tid >> 5);       // global row index
    int i   = tid & 31;                          // 0..31 rotation pair index

    const int QROWS = Bb * Hh * Tt;
    float* base;
    int t;
    if (row < QROWS) {
        base = q + (size_t)row * Dd;
        t = row % Tt;
    } else {
        int r2 = row - QROWS;
        base = k + (size_t)r2 * Dd;
        t = r2 % Tt;
    }
    // inv_freq = 10000^(-2i/64)
    float inv = exp2f(-(float)i * (2.0f / 64.0f) * 13.287712379549449f);
    float ang = (float)t * inv;
    float c = cosf(ang), s = sinf(ang);
    float x0 = base[i];
    float x1 = base[i + 32];
    base[i]      = x0 * c - x1 * s;
    base[i + 32] = x1 * c + x0 * s;
}

// ---------------- causal GQA flash attention --------------------------------
// grid: (T/32, H, B), block 256. BM=32 queries, BN=64 keys per tile.
// thread: lane = qi (0..31), w = tid/32 (0..7) owns keys j in [w*8, w*8+8)
// and output dims d in [w*8, w*8+8).
__global__ void attn_kernel(const float* __restrict__ q,
                            const float* __restrict__ k,
                            const float* __restrict__ v,
                            float* __restrict__ y)
{
    extern __shared__ float sm[];
    float* q_s  = sm;                    // 32*65
    float* k_s  = q_s + 32 * 65;         // 64*64
    float* v_s  = k_s + 64 * 64;         // 64*64
    float* p_s  = v_s + 64 * 64;         // 32*65
    float* red1 = p_s + 32 * 65;         // 8*32
    float* red2 = red1 + 8 * 32;         // 8*32

    int tid  = threadIdx.x;
    int lane = tid & 31;   // query row within tile
    int w    = tid >> 5;   // 0..7
    int q0   = blockIdx.x * 32;
    int h    = blockIdx.y;
    int b    = blockIdx.z;
    int kvh  = h / REPr;

    // load Q tile (pre-scaled by 1/sqrt(D))
    const float* qbase = q + (((size_t)b * Hh + h) * Tt + q0) * Dd;
    {
        int qi = tid >> 3;
        int d0 = (tid & 7) * 8;
        #pragma unroll
        for (int l = 0; l < 8; l++)
            q_s[qi * 65 + d0 + l] = qbase[qi * 64 + d0 + l] * 0.125f;
    }

    float m_i = -1e30f, l_i = 0.f;
    float o[8];
    #pragma unroll
    for (int i = 0; i < 8; i++) o[i] = 0.f;

    const float* kb = k + ((size_t)b * KVh + kvh) * Tt * Dd;
    const float* vb = v + ((size_t)b * KVh + kvh) * Tt * Dd;

    for (int kt0 = 0; kt0 < q0 + 32; kt0 += 64) {
        __syncthreads();  // q_s ready (iter 0); prev PV reads done (iter>0)
        // load K/V tiles: 64x64 each, 16 floats/thread
        {
            int j  = tid >> 2;
            int d0 = (tid & 3) * 16;
            #pragma unroll
            for (int l = 0; l < 16; l += 4) {
                *(float4*)(&k_s[j * 64 + d0 + l]) =
                    *(const float4*)(kb + (size_t)(kt0 + j) * 64 + d0 + l);
                *(float4*)(&v_s[j * 64 + d0 + l]) =
                    *(const float4*)(vb + (size_t)(kt0 + j) * 64 + d0 + l);
            }
        }
        __syncthreads();

        // scores for (qi=lane, j = w*8+jj)
        float acc[8];
        #pragma unroll
        for (int jj = 0; jj < 8; jj++) acc[jj] = 0.f;
        #pragma unroll 8
        for (int kk = 0; kk < 64; kk++) {
            float qv = q_s[lane * 65 + kk];
            #pragma unroll
            for (int jj = 0; jj < 8; jj++)
                acc[jj] += qv * k_s[(w * 8 + jj) * 64 + kk];
        }

        // causal mask
        int qg = q0 + lane;
        #pragma unroll
        for (int jj = 0; jj < 8; jj++)
            if (kt0 + w * 8 + jj > qg) acc[jj] = -1e30f;

        // row max (cross-warp via smem)
        float pm = acc[0];
        #pragma unroll
        for (int jj = 1; jj < 8; jj++) pm = fmaxf(pm, acc[jj]);
        red1[w * 32 + lane] = pm;
        __syncthreads();
        float m_new = m_i;
        #pragma unroll
        for (int ww = 0; ww < 8; ww++) m_new = fmaxf(m_new, red1[ww * 32 + lane]);

        // p = exp(s - m_new), partial row sum
        float ps = 0.f;
        #pragma unroll
        for (int jj = 0; jj < 8; jj++) {
            float pv = __expf(acc[jj] - m_new);
            p_s[lane * 65 + w * 8 + jj] = pv;
            ps += pv;
        }
        red2[w * 32 + lane] = ps;

        float factor = __expf(m_i - m_new);
        m_i = m_new;
        #pragma unroll
        for (int i = 0; i < 8; i++) o[i] *= factor;
        __syncthreads();  // p_s + red2 visible

        float lsum = 0.f;
        #pragma unroll
        for (int ww = 0; ww < 8; ww++) lsum += red2[ww * 32 + lane];
        l_i = l_i * factor + lsum;

        // o(qi, d=w*8+dd) += sum_j p(qi,j) * v(j,d)
        #pragma unroll 4
        for (int j = 0; j < 64; j++) {
            float pj = p_s[lane * 65 + j];
            #pragma unroll
            for (int dd = 0; dd < 8; dd++)
                o[dd] += pj * v_s[j * 64 + w * 8 + dd];
        }
    }

    float inv_l = 1.f / l_i;
    // y layout [B,T,H,D] so Wo GEMM sees plain [M, C]
    float* yb = y + (((size_t)b * Tt + q0 + lane) * Hh + h) * Dd + w * 8;
    #pragma unroll
    for (int dd = 0; dd < 8; dd++) yb[dd] = o[dd] * inv_l;
}

// ---------------- launcher ---------------------------------------------------
extern "C" void kernel_launch(void* const* d_in, const int* in_sizes, int n_in,
                              void* d_out, int out_size)
{
    const float* x  = (const float*)d_in[0];
    const float* Wq = (const float*)d_in[1];
    const float* Wk = (const float*)d_in[2];
    const float* Wv = (const float*)d_in[3];
    const float* Wo = (const float*)d_in[4];
    float* out = (float*)d_out;

    float *qp, *kp, *vp, *yp;
    cudaGetSymbolAddress((void**)&qp, g_q);
    cudaGetSymbolAddress((void**)&kp, g_k);
    cudaGetSymbolAddress((void**)&vp, g_v);
    cudaGetSymbolAddress((void**)&yp, g_y);

    const int M = Bb * Tt;  // 49152

    // QKV projections (with layout remap)
    gemm_kernel<<<dim3((Hh * Dd) / 64, M / 64), 256>>>(x, Wq, qp, M, Hh * Dd, Cc, Hh);
    gemm_kernel<<<dim3((KVh * Dd) / 64, M / 64), 256>>>(x, Wk, kp, M, KVh * Dd, Cc, KVh);
    gemm_kernel<<<dim3((KVh * Dd) / 64, M / 64), 256>>>(x, Wv, vp, M, KVh * Dd, Cc, KVh);

    // RoPE on q and k
    {
        int rows = Bb * Hh * Tt + Bb * KVh * Tt;  // 294912, divisible by 8
        rope_kernel<<<rows / 8, 256>>>(qp, kp);
    }

    // attention
    {
        size_t smem = (32 * 65 + 64 * 64 + 64 * 64 + 32 * 65 + 8 * 32 + 8 * 32) * sizeof(float);
        static bool attr_set = false;
        if (!attr_set) {
            cudaFuncSetAttribute(attn_kernel, cudaFuncAttributeMaxDynamicSharedMemorySize,
                                 (int)smem);
            attr_set = true;
        }
        attn_kernel<<<dim3(Tt / 32, Hh, Bb), 256, smem>>>(qp, kp, vp, yp);
    }

    // output projection
    gemm_kernel<<<dim3(Cc / 64, M / 64), 256>>>(yp, Wo, out, M, Cc, Cc, 0);
}

// round 8
// speedup vs baseline: 1.3119x; 1.3119x over previous
#include <cuda_runtime.h>
#include <cuda_bf16.h>
#include <cstdint>
#include <math.h>

#define Bb   128
#define Tt   384
#define Cc   256
#define Hh   4
#define KVh  2
#define Dd   64
#define REPr 2

// ===================== scratch (static device globals) =======================
__device__ __align__(16) float g_q[(size_t)Bb * Hh * Tt * Dd];   // [B,H,T,D]
__device__ __align__(16) float g_k[(size_t)Bb * KVh * Tt * Dd];  // [B,KV,T,D]
__device__ __align__(16) float g_v[(size_t)Bb * KVh * Tt * Dd];  // [B,KV,T,D]
__device__ __align__(16) float g_y[(size_t)Bb * Tt * Cc];        // [B,T,H*D]
__device__ __align__(16) __nv_bfloat16 g_wqkv_hi[512 * 256];     // W^T packed, hi
__device__ __align__(16) __nv_bfloat16 g_wqkv_lo[512 * 256];
__device__ __align__(16) __nv_bfloat16 g_wo_hi[256 * 256];       // Wo^T, hi
__device__ __align__(16) __nv_bfloat16 g_wo_lo[256 * 256];
__device__ __align__(16) float g_cos[Tt * 32];
__device__ __align__(16) float g_sin[Tt * 32];

// ===================== small helpers ========================================
__device__ __forceinline__ uint32_t smem_to_u32(const void* p) {
    uint32_t a;
    asm("{ .reg .u64 t; cvta.to.shared.u64 t, %1; cvt.u32.u64 %0, t; }"
        : "=r"(a) : "l"(p));
    return a;
}

// XOR-16B swizzle for 128B rows (8 units): conflict-free ldmatrix
__device__ __forceinline__ uint32_t swz(int row, int col_bytes) {
    return (uint32_t)(row * 128 + (((col_bytes >> 4) ^ (row & 7)) << 4) +
                      (col_bytes & 15));
}

__device__ __forceinline__ void split_pack2(float a, float b,
                                            uint32_t& hi, uint32_t& lo)
{
    __nv_bfloat16 ha = __float2bfloat16(a);
    __nv_bfloat16 hb = __float2bfloat16(b);
    __nv_bfloat16 la = __float2bfloat16(a - __bfloat162float(ha));
    __nv_bfloat16 lb = __float2bfloat16(b - __bfloat162float(hb));
    hi = ((uint32_t)__bfloat16_as_ushort(hb) << 16) | __bfloat16_as_ushort(ha);
    lo = ((uint32_t)__bfloat16_as_ushort(lb) << 16) | __bfloat16_as_ushort(la);
}

#define LDSM_X4(r0, r1, r2, r3, addr) \
    asm volatile("ldmatrix.sync.aligned.m8n8.x4.shared.b16 {%0,%1,%2,%3}, [%4];" \
        : "=r"(r0), "=r"(r1), "=r"(r2), "=r"(r3) : "r"(addr))

#define MMA_BF16(c, a, b0, b1) \
    asm volatile("mma.sync.aligned.m16n8k16.row.col.f32.bf16.bf16.f32 " \
        "{%0,%1,%2,%3}, {%4,%5,%6,%7}, {%8,%9}, {%0,%1,%2,%3};" \
        : "+f"((c)[0]), "+f"((c)[1]), "+f"((c)[2]), "+f"((c)[3]) \
        : "r"((a)[0]), "r"((a)[1]), "r"((a)[2]), "r"((a)[3]), \
          "r"(b0), "r"(b1))

// ===================== prep: weight transpose/pack/split + rope tables ======
__global__ void prep_kernel(const float* __restrict__ Wq,
                            const float* __restrict__ Wk,
                            const float* __restrict__ Wv,
                            const float* __restrict__ Wo)
{
    int idx = blockIdx.x * 256 + threadIdx.x;
    if (idx < 131072) {                              // wqkv^T pack+split
        int n = idx >> 8, k = idx & 255;
        float v;
        if (n < 256)      v = Wq[k * 256 + n];
        else if (n < 384) v = Wk[k * 128 + (n - 256)];
        else              v = Wv[k * 128 + (n - 384)];
        __nv_bfloat16 h = __float2bfloat16(v);
        g_wqkv_hi[idx] = h;
        g_wqkv_lo[idx] = __float2bfloat16(v - __bfloat162float(h));
    } else if (idx < 131072 + 65536) {               // wo^T split
        int j = idx - 131072;
        int n = j >> 8, k = j & 255;
        float v = Wo[k * 256 + n];
        __nv_bfloat16 h = __float2bfloat16(v);
        g_wo_hi[j] = h;
        g_wo_lo[j] = __float2bfloat16(v - __bfloat162float(h));
    } else if (idx < 131072 + 65536 + Tt * 32) {     // rope tables
        int j = idx - 196608;
        int t = j >> 5, i = j & 31;
        float inv = exp2f(-(float)i * (2.0f / 64.0f) * 13.287712379549449f);
        float ang = (float)t * inv;
        g_cos[j] = cosf(ang);
        g_sin[j] = sinf(ang);
    }
}

// ===================== HMMA GEMM (bf16x3 split, mma.sync) ====================
// C[M, Ntot] = A[M,256] @ B^T,  B pre-split bf16 [Ntot][256] (hi, lo).
// CTA tile 128x128, K in 4 chunks of 64. 8 warps in 2(m) x 4(n), warp tile 64x32.
// mode 0: plain fp32 out [M, Ntot].  mode 1: QKV epilogue (head remap + RoPE).
__global__ __launch_bounds__(256, 2)
void gemm_mma_kernel(const float* __restrict__ A,
                     const __nv_bfloat16* __restrict__ Bhi,
                     const __nv_bfloat16* __restrict__ Blo,
                     float* __restrict__ outp,
                     float* __restrict__ qp,
                     float* __restrict__ kp,
                     float* __restrict__ vp,
                     const float* __restrict__ ctab,
                     const float* __restrict__ stab,
                     int mode)
{
    extern __shared__ char smem[];
    // tiles: a_hi [0,16K)  a_lo [16K,32K)  b_hi [32K,48K)  b_lo [48K,64K)
    char* a_hi = smem;
    char* a_lo = smem + 16384;
    char* b_hi = smem + 32768;
    char* b_lo = smem + 49152;
    uint32_t sb   = smem_to_u32(smem);
    uint32_t sbAh = sb, sbAl = sb + 16384, sbBh = sb + 32768, sbBl = sb + 49152;

    int tid  = threadIdx.x;
    int wid  = tid >> 5, lane = tid & 31;
    int wm   = wid & 1;          // m-warp: 64 rows each
    int wn   = wid >> 1;         // n-warp: 32 cols each
    int m0   = blockIdx.y * 128;
    int n0   = blockIdx.x * 128;

    float acc[4][4][4];
    #pragma unroll
    for (int i = 0; i < 4; i++)
        #pragma unroll
        for (int j = 0; j < 4; j++)
            #pragma unroll
            for (int e = 0; e < 4; e++) acc[i][j][e] = 0.f;

    int lr = tid >> 1;             // load row 0..127
    int cb = (tid & 1) * 32;       // element col base within 64-chunk

    for (int kc = 0; kc < 4; kc++) {
        int kc0 = kc * 64;
        __syncthreads();
        // ---- A chunk: fp32 -> bf16 hi/lo split ----
        {
            const float4* arow =
                (const float4*)(A + (size_t)(m0 + lr) * 256 + kc0 + cb);
            #pragma unroll
            for (int j = 0; j < 8; j++) {
                float4 f = arow[j];
                uint32_t h01, l01, h23, l23;
                split_pack2(f.x, f.y, h01, l01);
                split_pack2(f.z, f.w, h23, l23);
                uint32_t off = swz(lr, (cb + 4 * j) * 2);
                *(uint2*)(a_hi + off) = make_uint2(h01, h23);
                *(uint2*)(a_lo + off) = make_uint2(l01, l23);
            }
        }
        // ---- B chunk: bf16 hi/lo direct ----
        {
            const uint4* bhr =
                (const uint4*)(Bhi + (size_t)(n0 + lr) * 256 + kc0 + cb);
            const uint4* blr =
                (const uint4*)(Blo + (size_t)(n0 + lr) * 256 + kc0 + cb);
            #pragma unroll
            for (int j = 0; j < 4; j++) {
                uint4 hv = bhr[j];
                uint4 lv = blr[j];
                uint32_t off = swz(lr, (cb + 8 * j) * 2);
                *(uint4*)(b_hi + off) = hv;
                *(uint4*)(b_lo + off) = lv;
            }
        }
        __syncthreads();

        // ---- compute: 4 k16-steps ----
        #pragma unroll
        for (int ks = 0; ks < 4; ks++) {
            // lane addressing
            int ar = wm * 64 + (lane & 15);                 // + i*16
            int ac = (ks * 16 + ((lane >> 4) << 3)) * 2;    // bytes
            int br = wn * 32 + (lane & 7) + ((lane >> 4) << 3);  // + g*16
            int bc = (ks * 16 + (((lane >> 3) & 1) << 3)) * 2;

            uint32_t rbh[8], rbl[8], ra[4][4];
            #pragma unroll
            for (int g = 0; g < 2; g++) {
                uint32_t addr = sbBh + swz(br + g * 16, bc);
                LDSM_X4(rbh[g*4+0], rbh[g*4+1], rbh[g*4+2], rbh[g*4+3], addr);
                addr = sbBl + swz(br + g * 16, bc);
                LDSM_X4(rbl[g*4+0], rbl[g*4+1], rbl[g*4+2], rbl[g*4+3], addr);
            }
            #pragma unroll
            for (int i = 0; i < 4; i++) {
                uint32_t addr = sbAh + swz(ar + i * 16, ac);
                LDSM_X4(ra[i][0], ra[i][1], ra[i][2], ra[i][3], addr);
            }
            // hi @ hi  and  hi @ lo
            #pragma unroll
            for (int i = 0; i < 4; i++)
                #pragma unroll
                for (int j = 0; j < 4; j++) {
                    int g = j >> 1, p = (j & 1) * 2;
                    MMA_BF16(acc[i][j], ra[i], rbh[g*4+p], rbh[g*4+p+1]);
                    MMA_BF16(acc[i][j], ra[i], rbl[g*4+p], rbl[g*4+p+1]);
                }
            // lo @ hi
            #pragma unroll
            for (int i = 0; i < 4; i++) {
                uint32_t addr = sbAl + swz(ar + i * 16, ac);
                LDSM_X4(ra[i][0], ra[i][1], ra[i][2], ra[i][3], addr);
            }
            #pragma unroll
            for (int i = 0; i < 4; i++)
                #pragma unroll
                for (int j = 0; j < 4; j++) {
                    int g = j >> 1, p = (j & 1) * 2;
                    MMA_BF16(acc[i][j], ra[i], rbh[g*4+p], rbh[g*4+p+1]);
                }
        }
    }

    // ---- C to smem (reuse tile memory), stride 136 floats ----
    __syncthreads();
    float* Csm = (float*)smem;
    #pragma unroll
    for (int i = 0; i < 4; i++)
        #pragma unroll
        for (int j = 0; j < 4; j++) {
            int row = wm * 64 + i * 16 + (lane >> 2);
            int col = wn * 32 + j * 8 + (lane & 3) * 2;
            *(float2*)&Csm[(size_t)row * 136 + col] =
                make_float2(acc[i][j][0], acc[i][j][1]);
            *(float2*)&Csm[(size_t)(row + 8) * 136 + col] =
                make_float2(acc[i][j][2], acc[i][j][3]);
        }
    __syncthreads();

    // ---- epilogue ----
    int r    = tid >> 1;
    int half = tid & 1;
    int m    = m0 + r;
    const float* csrc = Csm + (size_t)r * 136 + half * 64;

    if (mode == 0) {
        float* dst = outp + (size_t)m * 256 + n0 + half * 64;
        #pragma unroll
        for (int j = 0; j < 16; j++)
            *(float4*)(dst + 4 * j) = *(const float4*)(csrc + 4 * j);
    } else {
        int b = m / Tt, t = m % Tt;
        int g = (n0 >> 6) + half;   // 0..3 Q heads, 4..5 K kv, 6..7 V kv
        if (g < 6) {
            float cs[32], sn[32];
            #pragma unroll
            for (int j = 0; j < 8; j++) {
                *(float4*)(cs + 4 * j) = *(const float4*)(ctab + t * 32 + 4 * j);
                *(float4*)(sn + 4 * j) = *(const float4*)(stab + t * 32 + 4 * j);
            }
            float* dst = (g < 4)
                ? qp + (((size_t)b * Hh + g) * Tt + t) * 64
                : kp + (((size_t)b * KVh + (g - 4)) * Tt + t) * 64;
            #pragma unroll
            for (int j = 0; j < 8; j++) {
                float4 x0 = *(const float4*)(csrc + 4 * j);
                float4 x1 = *(const float4*)(csrc + 32 + 4 * j);
                float4 o0, o1;
                o0.x = x0.x * cs[4*j+0] - x1.x * sn[4*j+0];
                o0.y = x0.y * cs[4*j+1] - x1.y * sn[4*j+1];
                o0.z = x0.z * cs[4*j+2] - x1.z * sn[4*j+2];
                o0.w = x0.w * cs[4*j+3] - x1.w * sn[4*j+3];
                o1.x = x1.x * cs[4*j+0] + x0.x * sn[4*j+0];
                o1.y = x1.y * cs[4*j+1] + x0.y * sn[4*j+1];
                o1.z = x1.z * cs[4*j+2] + x0.z * sn[4*j+2];
                o1.w = x1.w * cs[4*j+3] + x0.w * sn[4*j+3];
                *(float4*)(dst + 4 * j)      = o0;
                *(float4*)(dst + 32 + 4 * j) = o1;
            }
        } else {
            float* dst = vp + (((size_t)b * KVh + (g - 6)) * Tt + t) * 64;
            #pragma unroll
            for (int j = 0; j < 16; j++)
                *(float4*)(dst + 4 * j) = *(const float4*)(csrc + 4 * j);
        }
    }
}

// ===================== causal GQA flash attention (SIMT, validated) ==========
__global__ void attn_kernel(const float* __restrict__ q,
                            const float* __restrict__ k,
                            const float* __restrict__ v,
                            float* __restrict__ y)
{
    extern __shared__ float sm[];
    float* q_s  = sm;
    float* k_s  = q_s + 32 * 65;
    float* v_s  = k_s + 64 * 64;
    float* p_s  = v_s + 64 * 64;
    float* red1 = p_s + 32 * 65;
    float* red2 = red1 + 8 * 32;

    int tid  = threadIdx.x;
    int lane = tid & 31;
    int w    = tid >> 5;
    int q0   = blockIdx.x * 32;
    int h    = blockIdx.y;
    int b    = blockIdx.z;
    int kvh  = h / REPr;

    const float* qbase = q + (((size_t)b * Hh + h) * Tt + q0) * Dd;
    {
        int qi = tid >> 3;
        int d0 = (tid & 7) * 8;
        #pragma unroll
        for (int l = 0; l < 8; l++)
            q_s[qi * 65 + d0 + l] = qbase[qi * 64 + d0 + l] * 0.125f;
    }

    float m_i = -1e30f, l_i = 0.f;
    float o[8];
    #pragma unroll
    for (int i = 0; i < 8; i++) o[i] = 0.f;

    const float* kb = k + ((size_t)b * KVh + kvh) * Tt * Dd;
    const float* vb = v + ((size_t)b * KVh + kvh) * Tt * Dd;

    for (int kt0 = 0; kt0 < q0 + 32; kt0 += 64) {
        __syncthreads();
        {
            int j  = tid >> 2;
            int d0 = (tid & 3) * 16;
            #pragma unroll
            for (int l = 0; l < 16; l += 4) {
                *(float4*)(&k_s[j * 64 + d0 + l]) =
                    *(const float4*)(kb + (size_t)(kt0 + j) * 64 + d0 + l);
                *(float4*)(&v_s[j * 64 + d0 + l]) =
                    *(const float4*)(vb + (size_t)(kt0 + j) * 64 + d0 + l);
            }
        }
        __syncthreads();

        float acc[8];
        #pragma unroll
        for (int jj = 0; jj < 8; jj++) acc[jj] = 0.f;
        #pragma unroll 8
        for (int kk = 0; kk < 64; kk++) {
            float qv = q_s[lane * 65 + kk];
            #pragma unroll
            for (int jj = 0; jj < 8; jj++)
                acc[jj] += qv * k_s[(w * 8 + jj) * 64 + kk];
        }

        int qg = q0 + lane;
        #pragma unroll
        for (int jj = 0; jj < 8; jj++)
            if (kt0 + w * 8 + jj > qg) acc[jj] = -1e30f;

        float pm = acc[0];
        #pragma unroll
        for (int jj = 1; jj < 8; jj++) pm = fmaxf(pm, acc[jj]);
        red1[w * 32 + lane] = pm;
        __syncthreads();
        float m_new = m_i;
        #pragma unroll
        for (int ww = 0; ww < 8; ww++) m_new = fmaxf(m_new, red1[ww * 32 + lane]);

        float ps = 0.f;
        #pragma unroll
        for (int jj = 0; jj < 8; jj++) {
            float pv = __expf(acc[jj] - m_new);
            p_s[lane * 65 + w * 8 + jj] = pv;
            ps += pv;
        }
        red2[w * 32 + lane] = ps;

        float factor = __expf(m_i - m_new);
        m_i = m_new;
        #pragma unroll
        for (int i = 0; i < 8; i++) o[i] *= factor;
        __syncthreads();

        float lsum = 0.f;
        #pragma unroll
        for (int ww = 0; ww < 8; ww++) lsum += red2[ww * 32 + lane];
        l_i = l_i * factor + lsum;

        #pragma unroll 4
        for (int j = 0; j < 64; j++) {
            float pj = p_s[lane * 65 + j];
            #pragma unroll
            for (int dd = 0; dd < 8; dd++)
                o[dd] += pj * v_s[j * 64 + w * 8 + dd];
        }
    }

    float inv_l = 1.f / l_i;
    float* yb = y + (((size_t)b * Tt + q0 + lane) * Hh + h) * Dd + w * 8;
    #pragma unroll
    for (int dd = 0; dd < 8; dd++) yb[dd] = o[dd] * inv_l;
}

// ===================== launcher ==============================================
extern "C" void kernel_launch(void* const* d_in, const int* in_sizes, int n_in,
                              void* d_out, int out_size)
{
    const float* x  = (const float*)d_in[0];
    const float* Wq = (const float*)d_in[1];
    const float* Wk = (const float*)d_in[2];
    const float* Wv = (const float*)d_in[3];
    const float* Wo = (const float*)d_in[4];
    float* out = (float*)d_out;

    float *qp, *kp, *vp, *yp, *cosp, *sinp;
    __nv_bfloat16 *wqh, *wql, *woh, *wol;
    cudaGetSymbolAddress((void**)&qp, g_q);
    cudaGetSymbolAddress((void**)&kp, g_k);
    cudaGetSymbolAddress((void**)&vp, g_v);
    cudaGetSymbolAddress((void**)&yp, g_y);
    cudaGetSymbolAddress((void**)&cosp, g_cos);
    cudaGetSymbolAddress((void**)&sinp, g_sin);
    cudaGetSymbolAddress((void**)&wqh, g_wqkv_hi);
    cudaGetSymbolAddress((void**)&wql, g_wqkv_lo);
    cudaGetSymbolAddress((void**)&woh, g_wo_hi);
    cudaGetSymbolAddress((void**)&wol, g_wo_lo);

    const int M = Bb * Tt;                 // 49152
    const int gemm_smem = 69632;           // 64K tiles / 128x136 fp32 C
    const int asmem = (32*65 + 64*64 + 64*64 + 32*65 + 8*32 + 8*32) * 4;

    cudaFuncSetAttribute(gemm_mma_kernel,
                         cudaFuncAttributeMaxDynamicSharedMemorySize, gemm_smem);
    cudaFuncSetAttribute(attn_kernel,
                         cudaFuncAttributeMaxDynamicSharedMemorySize, asmem);

    // 1. weight pack/transpose/split + rope tables
    prep_kernel<<<816, 256>>>(Wq, Wk, Wv, Wo);

    // 2. fused QKV projection + RoPE epilogue (N = 512)
    gemm_mma_kernel<<<dim3(4, M / 128), 256, gemm_smem>>>(
        x, wqh, wql, nullptr, qp, kp, vp, cosp, sinp, 1);

    // 3. attention
    attn_kernel<<<dim3(Tt / 32, Hh, Bb), 256, asmem>>>(qp, kp, vp, yp);

    // 4. output projection (N = 256)
    gemm_mma_kernel<<<dim3(2, M / 128), 256, gemm_smem>>>(
        yp, woh, wol, out, nullptr, nullptr, nullptr, nullptr, nullptr, 0);
}

// round 10
// speedup vs baseline: 2.4913x; 1.8990x over previous
#include <cuda_runtime.h>
#include <cuda_bf16.h>
#include <cstdint>
#include <math.h>

#define Bb   128
#define Tt   384
#define Cc   256
#define Hh   4
#define KVh  2
#define Dd   64
#define REPr 2

// ===================== scratch (static device globals) =======================
__device__ __align__(16) float g_y[(size_t)Bb * Tt * Cc];          // [B,T,H*D]
__device__ __align__(16) __nv_bfloat16 g_qh[(size_t)Bb * Hh * Tt * Dd];
__device__ __align__(16) __nv_bfloat16 g_ql[(size_t)Bb * Hh * Tt * Dd];
__device__ __align__(16) __nv_bfloat16 g_kh[(size_t)Bb * KVh * Tt * Dd];
__device__ __align__(16) __nv_bfloat16 g_kl[(size_t)Bb * KVh * Tt * Dd];
__device__ __align__(16) __nv_bfloat16 g_vh[(size_t)Bb * KVh * Tt * Dd];
__device__ __align__(16) __nv_bfloat16 g_vl[(size_t)Bb * KVh * Tt * Dd];
__device__ __align__(16) __nv_bfloat16 g_wqkv_hi[512 * 256];     // W^T packed, hi
__device__ __align__(16) __nv_bfloat16 g_wqkv_lo[512 * 256];
__device__ __align__(16) __nv_bfloat16 g_wo_hi[256 * 256];       // Wo^T, hi
__device__ __align__(16) __nv_bfloat16 g_wo_lo[256 * 256];
__device__ __align__(16) float g_cos[Tt * 32];
__device__ __align__(16) float g_sin[Tt * 32];

// ===================== small helpers ========================================
__device__ __forceinline__ uint32_t smem_to_u32(const void* p) {
    uint32_t a;
    asm("{ .reg .u64 t; cvta.to.shared.u64 t, %1; cvt.u32.u64 %0, t; }"
        : "=r"(a) : "l"(p));
    return a;
}

// XOR-16B swizzle for 128B rows (8 units): conflict-free ldmatrix
__device__ __forceinline__ uint32_t swz(int row, int col_bytes) {
    return (uint32_t)(row * 128 + (((col_bytes >> 4) ^ (row & 7)) << 4) +
                      (col_bytes & 15));
}

__device__ __forceinline__ void split_pack2(float a, float b,
                                            uint32_t& hi, uint32_t& lo)
{
    __nv_bfloat16 ha = __float2bfloat16(a);
    __nv_bfloat16 hb = __float2bfloat16(b);
    __nv_bfloat16 la = __float2bfloat16(a - __bfloat162float(ha));
    __nv_bfloat16 lb = __float2bfloat16(b - __bfloat162float(hb));
    hi = ((uint32_t)__bfloat16_as_ushort(hb) << 16) | __bfloat16_as_ushort(ha);
    lo = ((uint32_t)__bfloat16_as_ushort(lb) << 16) | __bfloat16_as_ushort(la);
}

#define LDSM_X4(r0, r1, r2, r3, addr) \
    asm volatile("ldmatrix.sync.aligned.m8n8.x4.shared.b16 {%0,%1,%2,%3}, [%4];" \
        : "=r"(r0), "=r"(r1), "=r"(r2), "=r"(r3) : "r"(addr))

#define LDSM_X4_T(r0, r1, r2, r3, addr) \
    asm volatile("ldmatrix.sync.aligned.m8n8.x4.trans.shared.b16 {%0,%1,%2,%3}, [%4];" \
        : "=r"(r0), "=r"(r1), "=r"(r2), "=r"(r3) : "r"(addr))

#define MMA_BF16(c, a, b0, b1) \
    asm volatile("mma.sync.aligned.m16n8k16.row.col.f32.bf16.bf16.f32 " \
        "{%0,%1,%2,%3}, {%4,%5,%6,%7}, {%8,%9}, {%0,%1,%2,%3};" \
        : "+f"((c)[0]), "+f"((c)[1]), "+f"((c)[2]), "+f"((c)[3]) \
        : "r"((a)[0]), "r"((a)[1]), "r"((a)[2]), "r"((a)[3]), \
          "r"(b0), "r"(b1))

// ===================== prep: weight transpose/pack/split + rope tables ======
__global__ void prep_kernel(const float* __restrict__ Wq,
                            const float* __restrict__ Wk,
                            const float* __restrict__ Wv,
                            const float* __restrict__ Wo)
{
    int idx = blockIdx.x * 256 + threadIdx.x;
    if (idx < 131072) {                              // wqkv^T pack+split
        int n = idx >> 8, k = idx & 255;
        float v;
        if (n < 256)      v = Wq[k * 256 + n];
        else if (n < 384) v = Wk[k * 128 + (n - 256)];
        else              v = Wv[k * 128 + (n - 384)];
        __nv_bfloat16 h = __float2bfloat16(v);
        g_wqkv_hi[idx] = h;
        g_wqkv_lo[idx] = __float2bfloat16(v - __bfloat162float(h));
    } else if (idx < 131072 + 65536) {               // wo^T split
        int j = idx - 131072;
        int n = j >> 8, k = j & 255;
        float v = Wo[k * 256 + n];
        __nv_bfloat16 h = __float2bfloat16(v);
        g_wo_hi[j] = h;
        g_wo_lo[j] = __float2bfloat16(v - __bfloat162float(h));
    } else if (idx < 131072 + 65536 + Tt * 32) {     // rope tables
        int j = idx - 196608;
        int t = j >> 5, i = j & 31;
        float inv = exp2f(-(float)i * (2.0f / 64.0f) * 13.287712379549449f);
        float ang = (float)t * inv;
        g_cos[j] = cosf(ang);
        g_sin[j] = sinf(ang);
    }
}

// ===================== HMMA GEMM (bf16x3 split, mma.sync) ====================
// C[M, Ntot] = A[M,256] @ B^T,  B pre-split bf16 [Ntot][256] (hi, lo).
// CTA tile 128x128, K in 4 chunks of 64. 8 warps in 2(m) x 4(n), warp tile 64x32.
// mode 0: plain fp32 out.  mode 1: QKV epilogue -> rope + split bf16 hi/lo out.
__global__ __launch_bounds__(256, 2)
void gemm_mma_kernel(const float* __restrict__ A,
                     const __nv_bfloat16* __restrict__ Bhi,
                     const __nv_bfloat16* __restrict__ Blo,
                     float* __restrict__ outp,
                     __nv_bfloat16* __restrict__ qh, __nv_bfloat16* __restrict__ ql,
                     __nv_bfloat16* __restrict__ kh, __nv_bfloat16* __restrict__ kl,
                     __nv_bfloat16* __restrict__ vh, __nv_bfloat16* __restrict__ vl,
                     const float* __restrict__ ctab,
                     const float* __restrict__ stab,
                     int mode)
{
    extern __shared__ char smem[];
    char* a_hi = smem;
    char* a_lo = smem + 16384;
    char* b_hi = smem + 32768;
    char* b_lo = smem + 49152;
    uint32_t sb   = smem_to_u32(smem);
    uint32_t sbAh = sb, sbAl = sb + 16384, sbBh = sb + 32768, sbBl = sb + 49152;

    int tid  = threadIdx.x;
    int wid  = tid >> 5, lane = tid & 31;
    int wm   = wid & 1;
    int wn   = wid >> 1;
    int m0   = blockIdx.y * 128;
    int n0   = blockIdx.x * 128;

    float acc[4][4][4];
    #pragma unroll
    for (int i = 0; i < 4; i++)
        #pragma unroll
        for (int j = 0; j < 4; j++)
            #pragma unroll
            for (int e = 0; e < 4; e++) acc[i][j][e] = 0.f;

    int lr = tid >> 1;
    int cb = (tid & 1) * 32;

    for (int kc = 0; kc < 4; kc++) {
        int kc0 = kc * 64;
        __syncthreads();
        {
            const float4* arow =
                (const float4*)(A + (size_t)(m0 + lr) * 256 + kc0 + cb);
            #pragma unroll
            for (int j = 0; j < 8; j++) {
                float4 f = arow[j];
                uint32_t h01, l01, h23, l23;
                split_pack2(f.x, f.y, h01, l01);
                split_pack2(f.z, f.w, h23, l23);
                uint32_t off = swz(lr, (cb + 4 * j) * 2);
                *(uint2*)(a_hi + off) = make_uint2(h01, h23);
                *(uint2*)(a_lo + off) = make_uint2(l01, l23);
            }
        }
        {
            const uint4* bhr =
                (const uint4*)(Bhi + (size_t)(n0 + lr) * 256 + kc0 + cb);
            const uint4* blr =
                (const uint4*)(Blo + (size_t)(n0 + lr) * 256 + kc0 + cb);
            #pragma unroll
            for (int j = 0; j < 4; j++) {
                uint4 hv = bhr[j];
                uint4 lv = blr[j];
                uint32_t off = swz(lr, (cb + 8 * j) * 2);
                *(uint4*)(b_hi + off) = hv;
                *(uint4*)(b_lo + off) = lv;
            }
        }
        __syncthreads();

        #pragma unroll
        for (int ks = 0; ks < 4; ks++) {
            int ar = wm * 64 + (lane & 15);
            int ac = (ks * 16 + ((lane >> 4) << 3)) * 2;
            int br = wn * 32 + (lane & 7) + ((lane >> 4) << 3);
            int bc = (ks * 16 + (((lane >> 3) & 1) << 3)) * 2;

            uint32_t rbh[8], rbl[8], ra[4][4];
            #pragma unroll
            for (int g = 0; g < 2; g++) {
                uint32_t addr = sbBh + swz(br + g * 16, bc);
                LDSM_X4(rbh[g*4+0], rbh[g*4+1], rbh[g*4+2], rbh[g*4+3], addr);
                addr = sbBl + swz(br + g * 16, bc);
                LDSM_X4(rbl[g*4+0], rbl[g*4+1], rbl[g*4+2], rbl[g*4+3], addr);
            }
            #pragma unroll
            for (int i = 0; i < 4; i++) {
                uint32_t addr = sbAh + swz(ar + i * 16, ac);
                LDSM_X4(ra[i][0], ra[i][1], ra[i][2], ra[i][3], addr);
            }
            #pragma unroll
            for (int i = 0; i < 4; i++)
                #pragma unroll
                for (int j = 0; j < 4; j++) {
                    int g = j >> 1, p = (j & 1) * 2;
                    MMA_BF16(acc[i][j], ra[i], rbh[g*4+p], rbh[g*4+p+1]);
                    MMA_BF16(acc[i][j], ra[i], rbl[g*4+p], rbl[g*4+p+1]);
                }
            #pragma unroll
            for (int i = 0; i < 4; i++) {
                uint32_t addr = sbAl + swz(ar + i * 16, ac);
                LDSM_X4(ra[i][0], ra[i][1], ra[i][2], ra[i][3], addr);
            }
            #pragma unroll
            for (int i = 0; i < 4; i++)
                #pragma unroll
                for (int j = 0; j < 4; j++) {
                    int g = j >> 1, p = (j & 1) * 2;
                    MMA_BF16(acc[i][j], ra[i], rbh[g*4+p], rbh[g*4+p+1]);
                }
        }
    }

    // ---- C to smem, stride 136 floats ----
    __syncthreads();
    float* Csm = (float*)smem;
    #pragma unroll
    for (int i = 0; i < 4; i++)
        #pragma unroll
        for (int j = 0; j < 4; j++) {
            int row = wm * 64 + i * 16 + (lane >> 2);
            int col = wn * 32 + j * 8 + (lane & 3) * 2;
            *(float2*)&Csm[(size_t)row * 136 + col] =
                make_float2(acc[i][j][0], acc[i][j][1]);
            *(float2*)&Csm[(size_t)(row + 8) * 136 + col] =
                make_float2(acc[i][j][2], acc[i][j][3]);
        }
    __syncthreads();

    int r    = tid >> 1;
    int half = tid & 1;
    int m    = m0 + r;
    const float* csrc = Csm + (size_t)r * 136 + half * 64;

    if (mode == 0) {
        float* dst = outp + (size_t)m * 256 + n0 + half * 64;
        #pragma unroll
        for (int j = 0; j < 16; j++)
            *(float4*)(dst + 4 * j) = *(const float4*)(csrc + 4 * j);
    } else {
        int b = m / Tt, t = m % Tt;
        int g = (n0 >> 6) + half;   // 0..3 Q heads, 4..5 K kv, 6..7 V kv
        float vals[64];
        if (g < 6) {
            #pragma unroll
            for (int i = 0; i < 32; i++) {
                float cs = ctab[t * 32 + i], sn = stab[t * 32 + i];
                float x0 = csrc[i], x1 = csrc[32 + i];
                vals[i]      = x0 * cs - x1 * sn;
                vals[i + 32] = x1 * cs + x0 * sn;
            }
            if (g < 4) {
                #pragma unroll
                for (int i = 0; i < 64; i++) vals[i] *= 0.125f;   // 1/sqrt(D)
            }
        } else {
            #pragma unroll
            for (int i = 0; i < 64; i++) vals[i] = csrc[i];
        }
        uint32_t hw[32], lw[32];
        #pragma unroll
        for (int jj = 0; jj < 32; jj++)
            split_pack2(vals[2 * jj], vals[2 * jj + 1], hw[jj], lw[jj]);

        size_t idx;
        __nv_bfloat16 *dh, *dl;
        if (g < 4)      { idx = (((size_t)b * Hh  + g      ) * Tt + t) * 64; dh = qh; dl = ql; }
        else if (g < 6) { idx = (((size_t)b * KVh + (g - 4)) * Tt + t) * 64; dh = kh; dl = kl; }
        else            { idx = (((size_t)b * KVh + (g - 6)) * Tt + t) * 64; dh = vh; dl = vl; }
        uint4* dh4 = (uint4*)(dh + idx);
        uint4* dl4 = (uint4*)(dl + idx);
        #pragma unroll
        for (int u = 0; u < 8; u++) {
            dh4[u] = make_uint4(hw[4*u], hw[4*u+1], hw[4*u+2], hw[4*u+3]);
            dl4[u] = make_uint4(lw[4*u], lw[4*u+1], lw[4*u+2], lw[4*u+3]);
        }
    }
}

// ===================== HMMA causal GQA flash attention =======================
// grid (T/128, H, B), 256 threads. Warp w owns q rows [w*16, w*16+16).
// Key tiles of 64; per-warp causal skip; softmax stats in-warp (quad shuffles).
__global__ __launch_bounds__(256)
void attn_mma_kernel(const __nv_bfloat16* __restrict__ qh,
                     const __nv_bfloat16* __restrict__ ql,
                     const __nv_bfloat16* __restrict__ kh,
                     const __nv_bfloat16* __restrict__ kl,
                     const __nv_bfloat16* __restrict__ vh,
                     const __nv_bfloat16* __restrict__ vl,
                     float* __restrict__ y)
{
    extern __shared__ char smem[];
    // qh 0..16K, ql 16..32K, kh 32..40K, kl 40..48K, vh 48..56K, vl 56..64K
    char* sQh = smem;
    char* sQl = smem + 16384;
    char* sKh = smem + 32768;
    char* sKl = smem + 40960;
    char* sVh = smem + 49152;
    char* sVl = smem + 57344;
    uint32_t ub   = smem_to_u32(smem);
    uint32_t uQh = ub, uQl = ub + 16384, uKh = ub + 32768, uKl = ub + 40960;
    uint32_t uVh = ub + 49152, uVl = ub + 57344;

    int tid  = threadIdx.x;
    int w    = tid >> 5, lane = tid & 31;
    int q0   = blockIdx.x * 128;
    int h    = blockIdx.y;
    int b    = blockIdx.z;
    int kvh  = h >> 1;

    // ---- stage Q tile (hi/lo) ----
    {
        int row = tid >> 1, hf = tid & 1;
        size_t src = (((size_t)b * Hh + h) * Tt + q0 + row) * 64 + hf * 32;
        const uint4* s0 = (const uint4*)(qh + src);
        const uint4* s1 = (const uint4*)(ql + src);
        #pragma unroll
        for (int j = 0; j < 4; j++) {
            uint32_t off = swz(row, hf * 64 + j * 16);
            *(uint4*)(sQh + off) = s0[j];
            *(uint4*)(sQl + off) = s1[j];
        }
    }
    __syncthreads();

    // ---- Q fragments (persist in regs) ----
    uint32_t qfh[4][4], qfl[4][4];
    #pragma unroll
    for (int ks = 0; ks < 4; ks++) {
        int ar = w * 16 + (lane & 15);
        int ac = (ks * 16 + ((lane >> 4) << 3)) * 2;
        LDSM_X4(qfh[ks][0], qfh[ks][1], qfh[ks][2], qfh[ks][3], uQh + swz(ar, ac));
        LDSM_X4(qfl[ks][0], qfl[ks][1], qfl[ks][2], qfl[ks][3], uQl + swz(ar, ac));
    }

    float o[8][4];
    #pragma unroll
    for (int i = 0; i < 8; i++)
        #pragma unroll
        for (int e = 0; e < 4; e++) o[i][e] = 0.f;
    float m0v = -1e30f, m1v = -1e30f, l0v = 0.f, l1v = 0.f;

    size_t kvbase = ((size_t)b * KVh + kvh) * Tt * 64;
    int ntiles = q0 / 64 + 2;
    int warp_max_row = q0 + w * 16 + 15;

    for (int kt = 0; kt < ntiles; kt++) {
        __syncthreads();
        // ---- stage K/V tiles (hi/lo) ----
        {
            int krow = tid >> 2, part = tid & 3;
            size_t src = kvbase + (size_t)(kt * 64 + krow) * 64 + part * 16;
            uint32_t o0 = swz(krow, part * 32);
            uint32_t o1 = swz(krow, part * 32 + 16);
            const uint4* p0 = (const uint4*)(kh + src);
            *(uint4*)(sKh + o0) = p0[0]; *(uint4*)(sKh + o1) = p0[1];
            const uint4* p1 = (const uint4*)(kl + src);
            *(uint4*)(sKl + o0) = p1[0]; *(uint4*)(sKl + o1) = p1[1];
            const uint4* p2 = (const uint4*)(vh + src);
            *(uint4*)(sVh + o0) = p2[0]; *(uint4*)(sVh + o1) = p2[1];
            const uint4* p3 = (const uint4*)(vl + src);
            *(uint4*)(sVl + o0) = p3[0]; *(uint4*)(sVl + o1) = p3[1];
        }
        __syncthreads();

        if (kt * 64 > warp_max_row) continue;   // fully masked for this warp

        // ---- S = Q @ K^T (bf16x3) ----
        float s[8][4];
        #pragma unroll
        for (int j = 0; j < 8; j++)
            #pragma unroll
            for (int e = 0; e < 4; e++) s[j][e] = 0.f;

        #pragma unroll
        for (int ks = 0; ks < 4; ks++) {
            int br = (lane & 7) + ((lane >> 4) << 3);
            int bc = (ks * 16 + (((lane >> 3) & 1) << 3)) * 2;
            uint32_t kbh[4][4], kbl[4][4];
            #pragma unroll
            for (int nf = 0; nf < 4; nf++) {
                uint32_t addr = uKh + swz(nf * 16 + br, bc);
                LDSM_X4(kbh[nf][0], kbh[nf][1], kbh[nf][2], kbh[nf][3], addr);
                addr = uKl + swz(nf * 16 + br, bc);
                LDSM_X4(kbl[nf][0], kbl[nf][1], kbl[nf][2], kbl[nf][3], addr);
            }
            #pragma unroll
            for (int nf = 0; nf < 4; nf++)
                #pragma unroll
                for (int p = 0; p < 2; p++) {
                    int j = nf * 2 + p;
                    MMA_BF16(s[j], qfh[ks], kbh[nf][2*p], kbh[nf][2*p+1]);
                    MMA_BF16(s[j], qfl[ks], kbh[nf][2*p], kbh[nf][2*p+1]);
                    MMA_BF16(s[j], qfh[ks], kbl[nf][2*p], kbl[nf][2*p+1]);
                }
        }

        // ---- causal mask ----
        int rowg = q0 + w * 16 + (lane >> 2);
        #pragma unroll
        for (int j = 0; j < 8; j++) {
            int colg = kt * 64 + j * 8 + 2 * (lane & 3);
            if (colg     > rowg)     s[j][0] = -1e30f;
            if (colg + 1 > rowg)     s[j][1] = -1e30f;
            if (colg     > rowg + 8) s[j][2] = -1e30f;
            if (colg + 1 > rowg + 8) s[j][3] = -1e30f;
        }

        // ---- online softmax (quad-shuffle row stats) ----
        float t0 = -1e30f, t1 = -1e30f;
        #pragma unroll
        for (int j = 0; j < 8; j++) {
            t0 = fmaxf(t0, fmaxf(s[j][0], s[j][1]));
            t1 = fmaxf(t1, fmaxf(s[j][2], s[j][3]));
        }
        t0 = fmaxf(t0, __shfl_xor_sync(0xffffffffu, t0, 1));
        t0 = fmaxf(t0, __shfl_xor_sync(0xffffffffu, t0, 2));
        t1 = fmaxf(t1, __shfl_xor_sync(0xffffffffu, t1, 1));
        t1 = fmaxf(t1, __shfl_xor_sync(0xffffffffu, t1, 2));
        float mn0 = fmaxf(m0v, t0), mn1 = fmaxf(m1v, t1);
        float f0 = __expf(m0v - mn0), f1 = __expf(m1v - mn1);
        m0v = mn0; m1v = mn1;

        float ps0 = 0.f, ps1 = 0.f;
        #pragma unroll
        for (int j = 0; j < 8; j++) {
            s[j][0] = __expf(s[j][0] - mn0); ps0 += s[j][0];
            s[j][1] = __expf(s[j][1] - mn0); ps0 += s[j][1];
            s[j][2] = __expf(s[j][2] - mn1); ps1 += s[j][2];
            s[j][3] = __expf(s[j][3] - mn1); ps1 += s[j][3];
        }
        ps0 += __shfl_xor_sync(0xffffffffu, ps0, 1);
        ps0 += __shfl_xor_sync(0xffffffffu, ps0, 2);
        ps1 += __shfl_xor_sync(0xffffffffu, ps1, 1);
        ps1 += __shfl_xor_sync(0xffffffffu, ps1, 2);
        l0v = l0v * f0 + ps0;
        l1v = l1v * f1 + ps1;

        #pragma unroll
        for (int dn = 0; dn < 8; dn++) {
            o[dn][0] *= f0; o[dn][1] *= f0;
            o[dn][2] *= f1; o[dn][3] *= f1;
        }

        // ---- P fragments (accumulator -> A-frag identity, hi/lo split) ----
        uint32_t pah[4][4], pal[4][4];
        #pragma unroll
        for (int kc = 0; kc < 4; kc++) {
            split_pack2(s[2*kc][0],   s[2*kc][1],   pah[kc][0], pal[kc][0]);
            split_pack2(s[2*kc][2],   s[2*kc][3],   pah[kc][1], pal[kc][1]);
            split_pack2(s[2*kc+1][0], s[2*kc+1][1], pah[kc][2], pal[kc][2]);
            split_pack2(s[2*kc+1][2], s[2*kc+1][3], pah[kc][3], pal[kc][3]);
        }

        // ---- O += P @ V (bf16x3), V frags via ldmatrix.trans ----
        #pragma unroll
        for (int kc = 0; kc < 4; kc++) {
            int vr = kc * 16 + (lane & 7) + ((lane >> 3) & 1) * 8;
            #pragma unroll
            for (int dn2 = 0; dn2 < 4; dn2++) {
                int vc = (dn2 * 16 + (lane >> 4) * 8) * 2;
                uint32_t vbh[4], vbl[4];
                LDSM_X4_T(vbh[0], vbh[1], vbh[2], vbh[3], uVh + swz(vr, vc));
                LDSM_X4_T(vbl[0], vbl[1], vbl[2], vbl[3], uVl + swz(vr, vc));
                #pragma unroll
                for (int p = 0; p < 2; p++) {
                    int dn = dn2 * 2 + p;
                    MMA_BF16(o[dn], pah[kc], vbh[2*p], vbh[2*p+1]);
                    MMA_BF16(o[dn], pal[kc], vbh[2*p], vbh[2*p+1]);
                    MMA_BF16(o[dn], pah[kc], vbl[2*p], vbl[2*p+1]);
                }
            }
        }
    }

    // ---- epilogue: y[B,T,H*D] fp32 ----
    float i0 = 1.f / l0v, i1 = 1.f / l1v;
    int row0 = q0 + w * 16 + (lane >> 2);
    int colb = h * 64 + 2 * (lane & 3);
    #pragma unroll
    for (int dn = 0; dn < 8; dn++) {
        *(float2*)&y[((size_t)b * Tt + row0) * 256 + colb + dn * 8] =
            make_float2(o[dn][0] * i0, o[dn][1] * i0);
        *(float2*)&y[((size_t)b * Tt + row0 + 8) * 256 + colb + dn * 8] =
            make_float2(o[dn][2] * i1, o[dn][3] * i1);
    }
}

// ===================== launcher ==============================================
extern "C" void kernel_launch(void* const* d_in, const int* in_sizes, int n_in,
                              void* d_out, int out_size)
{
    const float* x  = (const float*)d_in[0];
    const float* Wq = (const float*)d_in[1];
    const float* Wk = (const float*)d_in[2];
    const float* Wv = (const float*)d_in[3];
    const float* Wo = (const float*)d_in[4];
    float* out = (float*)d_out;

    float *yp, *cosp, *sinp;
    __nv_bfloat16 *wqh, *wql, *woh, *wol;
    __nv_bfloat16 *qhp, *qlp, *khp, *klp, *vhp, *vlp;
    cudaGetSymbolAddress((void**)&yp, g_y);
    cudaGetSymbolAddress((void**)&cosp, g_cos);
    cudaGetSymbolAddress((void**)&sinp, g_sin);
    cudaGetSymbolAddress((void**)&wqh, g_wqkv_hi);
    cudaGetSymbolAddress((void**)&wql, g_wqkv_lo);
    cudaGetSymbolAddress((void**)&woh, g_wo_hi);
    cudaGetSymbolAddress((void**)&wol, g_wo_lo);
    cudaGetSymbolAddress((void**)&qhp, g_qh);
    cudaGetSymbolAddress((void**)&qlp, g_ql);
    cudaGetSymbolAddress((void**)&khp, g_kh);
    cudaGetSymbolAddress((void**)&klp, g_kl);
    cudaGetSymbolAddress((void**)&vhp, g_vh);
    cudaGetSymbolAddress((void**)&vlp, g_vl);

    const int M = Bb * Tt;                 // 49152
    const int gemm_smem = 69632;
    const int attn_smem = 65536;

    cudaFuncSetAttribute(gemm_mma_kernel,
                         cudaFuncAttributeMaxDynamicSharedMemorySize, gemm_smem);
    cudaFuncSetAttribute(attn_mma_kernel,
                         cudaFuncAttributeMaxDynamicSharedMemorySize, attn_smem);

    // 1. weight pack/transpose/split + rope tables
    prep_kernel<<<816, 256>>>(Wq, Wk, Wv, Wo);

    // 2. fused QKV projection + RoPE + bf16 hi/lo split epilogue (N = 512)
    gemm_mma_kernel<<<dim3(4, M / 128), 256, gemm_smem>>>(
        x, wqh, wql, nullptr, qhp, qlp, khp, klp, vhp, vlp, cosp, sinp, 1);

    // 3. HMMA flash attention
    attn_mma_kernel<<<dim3(Tt / 128, Hh, Bb), 256, attn_smem>>>(
        qhp, qlp, khp, klp, vhp, vlp, yp);

    // 4. output projection (N = 256)
    gemm_mma_kernel<<<dim3(2, M / 128), 256, gemm_smem>>>(
        yp, woh, wol, out, nullptr, nullptr, nullptr, nullptr, nullptr, nullptr,
        nullptr, nullptr, 0);
}

// round 14
// speedup vs baseline: 2.7138x; 1.0893x over previous
#include <cuda_runtime.h>
#include <cuda_bf16.h>
#include <cstdint>
#include <math.h>

#define Bb   128
#define Tt   384
#define Cc   256
#define Hh   4
#define KVh  2
#define Dd   64
#define REPr 2

typedef __nv_bfloat16 bf16;

// ===================== scratch (static device globals) =======================
__device__ __align__(16) bf16 g_xh[(size_t)Bb * Tt * Cc];
__device__ __align__(16) bf16 g_xl[(size_t)Bb * Tt * Cc];
__device__ __align__(16) bf16 g_yh[(size_t)Bb * Tt * Cc];
__device__ __align__(16) bf16 g_yl[(size_t)Bb * Tt * Cc];
__device__ __align__(16) bf16 g_qh[(size_t)Bb * Hh * Tt * Dd];
__device__ __align__(16) bf16 g_ql[(size_t)Bb * Hh * Tt * Dd];
__device__ __align__(16) bf16 g_kh[(size_t)Bb * KVh * Tt * Dd];
__device__ __align__(16) bf16 g_kl[(size_t)Bb * KVh * Tt * Dd];
__device__ __align__(16) bf16 g_vh[(size_t)Bb * KVh * Tt * Dd];
__device__ __align__(16) bf16 g_vl[(size_t)Bb * KVh * Tt * Dd];
__device__ __align__(16) bf16 g_wqkv_hi[512 * 256];
__device__ __align__(16) bf16 g_wqkv_lo[512 * 256];
__device__ __align__(16) bf16 g_wo_hi[256 * 256];
__device__ __align__(16) bf16 g_wo_lo[256 * 256];
__device__ __align__(16) float g_cos[Tt * 32];
__device__ __align__(16) float g_sin[Tt * 32];

// ===================== small helpers ========================================
__device__ __forceinline__ uint32_t smem_to_u32(const void* p) {
    uint32_t a;
    asm("{ .reg .u64 t; cvta.to.shared.u64 t, %1; cvt.u32.u64 %0, t; }"
        : "=r"(a) : "l"(p));
    return a;
}

// XOR-16B swizzle for 128B rows: conflict-free ldmatrix
__device__ __forceinline__ uint32_t swz(int row, int col_bytes) {
    return (uint32_t)(row * 128 + (((col_bytes >> 4) ^ (row & 7)) << 4) +
                      (col_bytes & 15));
}

__device__ __forceinline__ void split_pack2(float a, float b,
                                            uint32_t& hi, uint32_t& lo)
{
    bf16 ha = __float2bfloat16(a);
    bf16 hb = __float2bfloat16(b);
    bf16 la = __float2bfloat16(a - __bfloat162float(ha));
    bf16 lb = __float2bfloat16(b - __bfloat162float(hb));
    hi = ((uint32_t)__bfloat16_as_ushort(hb) << 16) | __bfloat16_as_ushort(ha);
    lo = ((uint32_t)__bfloat16_as_ushort(lb) << 16) | __bfloat16_as_ushort(la);
}

#define LDSM_X4(r0, r1, r2, r3, addr) \
    asm volatile("ldmatrix.sync.aligned.m8n8.x4.shared.b16 {%0,%1,%2,%3}, [%4];" \
        : "=r"(r0), "=r"(r1), "=r"(r2), "=r"(r3) : "r"(addr))

#define LDSM_X4_T(r0, r1, r2, r3, addr) \
    asm volatile("ldmatrix.sync.aligned.m8n8.x4.trans.shared.b16 {%0,%1,%2,%3}, [%4];" \
        : "=r"(r0), "=r"(r1), "=r"(r2), "=r"(r3) : "r"(addr))

#define MMA_BF16(c, a, b0, b1) \
    asm volatile("mma.sync.aligned.m16n8k16.row.col.f32.bf16.bf16.f32 " \
        "{%0,%1,%2,%3}, {%4,%5,%6,%7}, {%8,%9}, {%0,%1,%2,%3};" \
        : "+f"((c)[0]), "+f"((c)[1]), "+f"((c)[2]), "+f"((c)[3]) \
        : "r"((a)[0]), "r"((a)[1]), "r"((a)[2]), "r"((a)[3]), \
          "r"(b0), "r"(b1))

#define CP16(dst, src) \
    asm volatile("cp.async.cg.shared.global [%0], [%1], 16;" \
        :: "r"(dst), "l"(src) : "memory")
#define CP_COMMIT() asm volatile("cp.async.commit_group;" ::: "memory")
#define CP_WAIT1()  asm volatile("cp.async.wait_group 1;" ::: "memory")
#define CP_WAIT0()  asm volatile("cp.async.wait_group 0;" ::: "memory")

// ===================== split x into bf16 hi/lo ===============================
__global__ void split_x_kernel(const float4* __restrict__ x4,
                               uint2* __restrict__ xh2,
                               uint2* __restrict__ xl2)
{
    size_t i = (size_t)blockIdx.x * 256 + threadIdx.x;
    float4 f = x4[i];
    uint32_t h01, l01, h23, l23;
    split_pack2(f.x, f.y, h01, l01);
    split_pack2(f.z, f.w, h23, l23);
    xh2[i] = make_uint2(h01, h23);
    xl2[i] = make_uint2(l01, l23);
}

// ===================== prep: weight transpose/pack/split + rope tables ======
__global__ void prep_kernel(const float* __restrict__ Wq,
                            const float* __restrict__ Wk,
                            const float* __restrict__ Wv,
                            const float* __restrict__ Wo)
{
    int idx = blockIdx.x * 256 + threadIdx.x;
    if (idx < 131072) {
        int n = idx >> 8, k = idx & 255;
        float v;
        if (n < 256)      v = Wq[k * 256 + n];
        else if (n < 384) v = Wk[k * 128 + (n - 256)];
        else              v = Wv[k * 128 + (n - 384)];
        bf16 h = __float2bfloat16(v);
        g_wqkv_hi[idx] = h;
        g_wqkv_lo[idx] = __float2bfloat16(v - __bfloat162float(h));
    } else if (idx < 131072 + 65536) {
        int j = idx - 131072;
        int n = j >> 8, k = j & 255;
        float v = Wo[k * 256 + n];
        bf16 h = __float2bfloat16(v);
        g_wo_hi[j] = h;
        g_wo_lo[j] = __float2bfloat16(v - __bfloat162float(h));
    } else if (idx < 131072 + 65536 + Tt * 32) {
        int j = idx - 196608;
        int t = j >> 5, i = j & 31;
        float inv = exp2f(-(float)i * (2.0f / 64.0f) * 13.287712379549449f);
        float ang = (float)t * inv;
        g_cos[j] = cosf(ang);
        g_sin[j] = sinf(ang);
    }
}

// ===================== HMMA GEMM, cp.async 2-stage pipeline ==================
// C[M,Ntot] = (Ah+Al)[M,256] @ (Bh+Bl)^T, pre-split bf16. CTA 128x128.
// K in 8 chunks of 32; smem row = 128B = [hi 64B | lo 64B], swizzled.
// Stage = 32KB (A 16K + B 16K); 2 stages. 8 warps 2(m) x 4(n).
// mode 0: fp32 out.  mode 1: QKV epilogue -> rope + split bf16 hi/lo q/k/v.
__global__ __launch_bounds__(256, 2)
void gemm_mma_kernel(const bf16* __restrict__ Ah, const bf16* __restrict__ Al,
                     const bf16* __restrict__ Bh, const bf16* __restrict__ Bl,
                     float* __restrict__ outp,
                     bf16* __restrict__ qh, bf16* __restrict__ ql,
                     bf16* __restrict__ kh, bf16* __restrict__ kl,
                     bf16* __restrict__ vh, bf16* __restrict__ vl,
                     const float* __restrict__ ctab,
                     const float* __restrict__ stab,
                     int mode)
{
    extern __shared__ char smem[];
    uint32_t sb = smem_to_u32(smem);
    const uint32_t SS = 32768;

    int tid  = threadIdx.x;
    int wid  = tid >> 5, lane = tid & 31;
    int wm   = wid & 1;
    int wn   = wid >> 1;
    int m0   = blockIdx.y * 128;
    int n0   = blockIdx.x * 128;

    float acc[4][4][4];
    #pragma unroll
    for (int i = 0; i < 4; i++)
        #pragma unroll
        for (int j = 0; j < 4; j++)
            #pragma unroll
            for (int e = 0; e < 4; e++) acc[i][j][e] = 0.f;

    // ---- cp.async source/dst mapping: 2 threads per row ----
    int lrow = tid >> 1, hf = tid & 1;
    const bf16* gAh = Ah + (size_t)(m0 + lrow) * 256 + hf * 16;
    const bf16* gAl = Al + (size_t)(m0 + lrow) * 256 + hf * 16;
    const bf16* gBh = Bh + (size_t)(n0 + lrow) * 256 + hf * 16;
    const bf16* gBl = Bl + (size_t)(n0 + lrow) * 256 + hf * 16;
    uint32_t dH0 = swz(lrow, hf * 32);
    uint32_t dH1 = swz(lrow, hf * 32 + 16);
    uint32_t dL0 = swz(lrow, 64 + hf * 32);
    uint32_t dL1 = swz(lrow, 64 + hf * 32 + 16);

    auto issue = [&](int c, int s) {
        uint32_t ab = sb + (uint32_t)s * SS;
        uint32_t bb = ab + 16384;
        const bf16* a0 = gAh + c * 32;
        const bf16* a1 = gAl + c * 32;
        const bf16* b0 = gBh + c * 32;
        const bf16* b1 = gBl + c * 32;
        CP16(ab + dH0, a0); CP16(ab + dH1, a0 + 8);
        CP16(ab + dL0, a1); CP16(ab + dL1, a1 + 8);
        CP16(bb + dH0, b0); CP16(bb + dH1, b0 + 8);
        CP16(bb + dL0, b1); CP16(bb + dL1, b1 + 8);
        CP_COMMIT();
    };

    auto compute = [&](int s) {
        uint32_t ab = sb + (uint32_t)s * SS;
        uint32_t bb = ab + 16384;
        #pragma unroll
        for (int ks = 0; ks < 2; ks++) {
            int ar  = wm * 64 + (lane & 15);
            int ach = (ks * 16 + ((lane >> 4) << 3)) * 2;
            int br  = wn * 32 + (lane & 7) + ((lane >> 4) << 3);
            int bch = (ks * 16 + (((lane >> 3) & 1) << 3)) * 2;

            uint32_t rbh[8], rbl[8], ra[4][4];
            #pragma unroll
            for (int g = 0; g < 2; g++) {
                LDSM_X4(rbh[g*4+0], rbh[g*4+1], rbh[g*4+2], rbh[g*4+3],
                        bb + swz(br + g * 16, bch));
                LDSM_X4(rbl[g*4+0], rbl[g*4+1], rbl[g*4+2], rbl[g*4+3],
                        bb + swz(br + g * 16, 64 + bch));
            }
            #pragma unroll
            for (int i = 0; i < 4; i++)
                LDSM_X4(ra[i][0], ra[i][1], ra[i][2], ra[i][3],
                        ab + swz(ar + i * 16, ach));
            #pragma unroll
            for (int i = 0; i < 4; i++)
                #pragma unroll
                for (int j = 0; j < 4; j++) {
                    int g = j >> 1, p = (j & 1) * 2;
                    MMA_BF16(acc[i][j], ra[i], rbh[g*4+p], rbh[g*4+p+1]);
                    MMA_BF16(acc[i][j], ra[i], rbl[g*4+p], rbl[g*4+p+1]);
                }
            #pragma unroll
            for (int i = 0; i < 4; i++)
                LDSM_X4(ra[i][0], ra[i][1], ra[i][2], ra[i][3],
                        ab + swz(ar + i * 16, 64 + ach));
            #pragma unroll
            for (int i = 0; i < 4; i++)
                #pragma unroll
                for (int j = 0; j < 4; j++) {
                    int g = j >> 1, p = (j & 1) * 2;
                    MMA_BF16(acc[i][j], ra[i], rbh[g*4+p], rbh[g*4+p+1]);
                }
        }
    };

    issue(0, 0);
    #pragma unroll 1
    for (int c = 0; c < 8; c++) {
        if (c < 7) { issue(c + 1, (c + 1) & 1); CP_WAIT1(); }
        else       { CP_WAIT0(); }
        __syncthreads();
        compute(c & 1);
        __syncthreads();
    }

    // ---- C to smem bounce (stride 136 floats) ----
    float* Csm = (float*)smem;
    #pragma unroll
    for (int i = 0; i < 4; i++)
        #pragma unroll
        for (int j = 0; j < 4; j++) {
            int row = wm * 64 + i * 16 + (lane >> 2);
            int col = wn * 32 + j * 8 + (lane & 3) * 2;
            *(float2*)&Csm[(size_t)row * 136 + col] =
                make_float2(acc[i][j][0], acc[i][j][1]);
            *(float2*)&Csm[(size_t)(row + 8) * 136 + col] =
                make_float2(acc[i][j][2], acc[i][j][3]);
        }
    __syncthreads();

    int r    = tid >> 1;
    int half = tid & 1;
    int m    = m0 + r;
    const float* csrc = Csm + (size_t)r * 136 + half * 64;

    if (mode == 0) {
        float* dst = outp + (size_t)m * 256 + n0 + half * 64;
        #pragma unroll
        for (int j = 0; j < 16; j++)
            *(float4*)(dst + 4 * j) = *(const float4*)(csrc + 4 * j);
    } else {
        int b = m / Tt, t = m % Tt;
        int g = (n0 >> 6) + half;   // 0..3 Q heads, 4..5 K kv, 6..7 V kv
        float vals[64];
        if (g < 6) {
            #pragma unroll
            for (int i = 0; i < 32; i++) {
                float cs = ctab[t * 32 + i], sn = stab[t * 32 + i];
                float x0 = csrc[i], x1 = csrc[32 + i];
                vals[i]      = x0 * cs - x1 * sn;
                vals[i + 32] = x1 * cs + x0 * sn;
            }
            if (g < 4) {
                #pragma unroll
                for (int i = 0; i < 64; i++) vals[i] *= 0.125f;   // 1/sqrt(D)
            }
        } else {
            #pragma unroll
            for (int i = 0; i < 64; i++) vals[i] = csrc[i];
        }
        uint32_t hw[32], lw[32];
        #pragma unroll
        for (int jj = 0; jj < 32; jj++)
            split_pack2(vals[2 * jj], vals[2 * jj + 1], hw[jj], lw[jj]);

        size_t idx;
        bf16 *dh, *dl;
        if (g < 4)      { idx = (((size_t)b * Hh  + g      ) * Tt + t) * 64; dh = qh; dl = ql; }
        else if (g < 6) { idx = (((size_t)b * KVh + (g - 4)) * Tt + t) * 64; dh = kh; dl = kl; }
        else            { idx = (((size_t)b * KVh + (g - 6)) * Tt + t) * 64; dh = vh; dl = vl; }
        uint4* dh4 = (uint4*)(dh + idx);
        uint4* dl4 = (uint4*)(dl + idx);
        #pragma unroll
        for (int u = 0; u < 8; u++) {
            dh4[u] = make_uint4(hw[4*u], hw[4*u+1], hw[4*u+2], hw[4*u+3]);
            dl4[u] = make_uint4(lw[4*u], lw[4*u+1], lw[4*u+2], lw[4*u+3]);
        }
    }
}

// ===================== HMMA causal GQA flash attention (cp.async 2-stage) ====
// grid (T/128, H, B), 256 threads. Warp w owns q rows [w*16, w*16+16).
// smem: Q 32KB | KV stage0 32KB | KV stage1 32KB  (each KV: Kh,Kl,Vh,Vl 8KB)
__global__ __launch_bounds__(256)
void attn_mma_kernel(const bf16* __restrict__ qh, const bf16* __restrict__ ql,
                     const bf16* __restrict__ kh, const bf16* __restrict__ kl,
                     const bf16* __restrict__ vh, const bf16* __restrict__ vl,
                     bf16* __restrict__ yh, bf16* __restrict__ yl)
{
    extern __shared__ char smem[];
    uint32_t ub  = smem_to_u32(smem);
    uint32_t uQh = ub, uQl = ub + 16384;

    int tid  = threadIdx.x;
    int w    = tid >> 5, lane = tid & 31;
    int q0   = blockIdx.x * 128;
    int h    = blockIdx.y;
    int b    = blockIdx.z;
    int kvh  = h >> 1;

    size_t kvbase = ((size_t)b * KVh + kvh) * Tt * 64;
    int ntiles = q0 / 64 + 2;

    // cp.async KV mapping: 4 threads per row
    int krow = tid >> 2, part = tid & 3;
    const bf16* gK0 = kh + kvbase + (size_t)krow * 64 + part * 16;
    const bf16* gK1 = kl + kvbase + (size_t)krow * 64 + part * 16;
    const bf16* gV0 = vh + kvbase + (size_t)krow * 64 + part * 16;
    const bf16* gV1 = vl + kvbase + (size_t)krow * 64 + part * 16;
    uint32_t d0 = swz(krow, part * 32);
    uint32_t d1 = swz(krow, part * 32 + 16);

    auto issueKV = [&](int kt, int s) {
        uint32_t base = ub + 32768 + (uint32_t)s * 32768;
        size_t off = (size_t)kt * 4096;
        CP16(base         + d0, gK0 + off); CP16(base         + d1, gK0 + off + 8);
        CP16(base +  8192 + d0, gK1 + off); CP16(base +  8192 + d1, gK1 + off + 8);
        CP16(base + 16384 + d0, gV0 + off); CP16(base + 16384 + d1, gV0 + off + 8);
        CP16(base + 24576 + d0, gV1 + off); CP16(base + 24576 + d1, gV1 + off + 8);
        CP_COMMIT();
    };

    // prefetch tile 0, then stage Q
    issueKV(0, 0);
    {
        int row = tid >> 1, hf = tid & 1;
        size_t src = (((size_t)b * Hh + h) * Tt + q0 + row) * 64 + hf * 32;
        const uint4* s0 = (const uint4*)(qh + src);
        const uint4* s1 = (const uint4*)(ql + src);
        #pragma unroll
        for (int j = 0; j < 4; j++) {
            uint32_t off = swz(row, hf * 64 + j * 16);
            *(uint4*)(smem + off)         = s0[j];
            *(uint4*)(smem + 16384 + off) = s1[j];
        }
    }
    __syncthreads();

    // Q fragments (persist in regs)
    uint32_t qfh[4][4], qfl[4][4];
    #pragma unroll
    for (int ks = 0; ks < 4; ks++) {
        int ar = w * 16 + (lane & 15);
        int ac = (ks * 16 + ((lane >> 4) << 3)) * 2;
        LDSM_X4(qfh[ks][0], qfh[ks][1], qfh[ks][2], qfh[ks][3], uQh + swz(ar, ac));
        LDSM_X4(qfl[ks][0], qfl[ks][1], qfl[ks][2], qfl[ks][3], uQl + swz(ar, ac));
    }

    float o[8][4];
    #pragma unroll
    for (int i = 0; i < 8; i++)
        #pragma unroll
        for (int e = 0; e < 4; e++) o[i][e] = 0.f;
    float m0v = -1e30f, m1v = -1e30f, l0v = 0.f, l1v = 0.f;

    int warp_max_row = q0 + w * 16 + 15;

    #pragma unroll 1
    for (int kt = 0; kt < ntiles; kt++) {
        if (kt + 1 < ntiles) { issueKV(kt + 1, (kt + 1) & 1); CP_WAIT1(); }
        else                 { CP_WAIT0(); }
        __syncthreads();

        if (kt * 64 <= warp_max_row) {
            uint32_t kb = ub + 32768 + (uint32_t)(kt & 1) * 32768;
            uint32_t uKh = kb, uKl = kb + 8192, uVh = kb + 16384, uVl = kb + 24576;

            // ---- S = Q @ K^T (bf16x3) ----
            float s[8][4];
            #pragma unroll
            for (int j = 0; j < 8; j++)
                #pragma unroll
                for (int e = 0; e < 4; e++) s[j][e] = 0.f;

            #pragma unroll
            for (int ks = 0; ks < 4; ks++) {
                int br = (lane & 7) + ((lane >> 4) << 3);
                int bc = (ks * 16 + (((lane >> 3) & 1) << 3)) * 2;
                uint32_t kbh[4][4], kbl[4][4];
                #pragma unroll
                for (int nf = 0; nf < 4; nf++) {
                    LDSM_X4(kbh[nf][0], kbh[nf][1], kbh[nf][2], kbh[nf][3],
                            uKh + swz(nf * 16 + br, bc));
                    LDSM_X4(kbl[nf][0], kbl[nf][1], kbl[nf][2], kbl[nf][3],
                            uKl + swz(nf * 16 + br, bc));
                }
                #pragma unroll
                for (int nf = 0; nf < 4; nf++)
                    #pragma unroll
                    for (int p = 0; p < 2; p++) {
                        int j = nf * 2 + p;
                        MMA_BF16(s[j], qfh[ks], kbh[nf][2*p], kbh[nf][2*p+1]);
                        MMA_BF16(s[j], qfl[ks], kbh[nf][2*p], kbh[nf][2*p+1]);
                        MMA_BF16(s[j], qfh[ks], kbl[nf][2*p], kbl[nf][2*p+1]);
                    }
            }

            // ---- causal mask ----
            int rowg = q0 + w * 16 + (lane >> 2);
            #pragma unroll
            for (int j = 0; j < 8; j++) {
                int colg = kt * 64 + j * 8 + 2 * (lane & 3);
                if (colg     > rowg)     s[j][0] = -1e30f;
                if (colg + 1 > rowg)     s[j][1] = -1e30f;
                if (colg     > rowg + 8) s[j][2] = -1e30f;
                if (colg + 1 > rowg + 8) s[j][3] = -1e30f;
            }

            // ---- online softmax (quad-shuffle row stats) ----
            float t0 = -1e30f, t1 = -1e30f;
            #pragma unroll
            for (int j = 0; j < 8; j++) {
                t0 = fmaxf(t0, fmaxf(s[j][0], s[j][1]));
                t1 = fmaxf(t1, fmaxf(s[j][2], s[j][3]));
            }
            t0 = fmaxf(t0, __shfl_xor_sync(0xffffffffu, t0, 1));
            t0 = fmaxf(t0, __shfl_xor_sync(0xffffffffu, t0, 2));
            t1 = fmaxf(t1, __shfl_xor_sync(0xffffffffu, t1, 1));
            t1 = fmaxf(t1, __shfl_xor_sync(0xffffffffu, t1, 2));
            float mn0 = fmaxf(m0v, t0), mn1 = fmaxf(m1v, t1);
            float f0 = __expf(m0v - mn0), f1 = __expf(m1v - mn1);
            m0v = mn0; m1v = mn1;

            float ps0 = 0.f, ps1 = 0.f;
            #pragma unroll
            for (int j = 0; j < 8; j++) {
                s[j][0] = __expf(s[j][0] - mn0); ps0 += s[j][0];
                s[j][1] = __expf(s[j][1] - mn0); ps0 += s[j][1];
                s[j][2] = __expf(s[j][2] - mn1); ps1 += s[j][2];
                s[j][3] = __expf(s[j][3] - mn1); ps1 += s[j][3];
            }
            ps0 += __shfl_xor_sync(0xffffffffu, ps0, 1);
            ps0 += __shfl_xor_sync(0xffffffffu, ps0, 2);
            ps1 += __shfl_xor_sync(0xffffffffu, ps1, 1);
            ps1 += __shfl_xor_sync(0xffffffffu, ps1, 2);
            l0v = l0v * f0 + ps0;
            l1v = l1v * f1 + ps1;

            #pragma unroll
            for (int dn = 0; dn < 8; dn++) {
                o[dn][0] *= f0; o[dn][1] *= f0;
                o[dn][2] *= f1; o[dn][3] *= f1;
            }

            // ---- P fragments (accumulator -> A-frag identity, hi/lo) ----
            uint32_t pah[4][4], pal[4][4];
            #pragma unroll
            for (int kc = 0; kc < 4; kc++) {
                split_pack2(s[2*kc][0],   s[2*kc][1],   pah[kc][0], pal[kc][0]);
                split_pack2(s[2*kc][2],   s[2*kc][3],   pah[kc][1], pal[kc][1]);
                split_pack2(s[2*kc+1][0], s[2*kc+1][1], pah[kc][2], pal[kc][2]);
                split_pack2(s[2*kc+1][2], s[2*kc+1][3], pah[kc][3], pal[kc][3]);
            }

            // ---- O += P @ V (bf16x3), V frags via ldmatrix.trans ----
            #pragma unroll
            for (int kc = 0; kc < 4; kc++) {
                int vr = kc * 16 + (lane & 7) + ((lane >> 3) & 1) * 8;
                #pragma unroll
                for (int dn2 = 0; dn2 < 4; dn2++) {
                    int vc = (dn2 * 16 + (lane >> 4) * 8) * 2;
                    uint32_t vbh[4], vbl[4];
                    LDSM_X4_T(vbh[0], vbh[1], vbh[2], vbh[3], uVh + swz(vr, vc));
                    LDSM_X4_T(vbl[0], vbl[1], vbl[2], vbl[3], uVl + swz(vr, vc));
                    #pragma unroll
                    for (int p = 0; p < 2; p++) {
                        int dn = dn2 * 2 + p;
                        MMA_BF16(o[dn], pah[kc], vbh[2*p], vbh[2*p+1]);
                        MMA_BF16(o[dn], pal[kc], vbh[2*p], vbh[2*p+1]);
                        MMA_BF16(o[dn], pah[kc], vbl[2*p], vbl[2*p+1]);
                    }
                }
            }
        }
        __syncthreads();
    }

    // ---- epilogue: y split bf16 hi/lo, layout [B,T,H*D] ----
    float i0 = 1.f / l0v, i1 = 1.f / l1v;
    int row0 = q0 + w * 16 + (lane >> 2);
    int colb = h * 64 + 2 * (lane & 3);
    #pragma unroll
    for (int dn = 0; dn < 8; dn++) {
        size_t off0 = ((size_t)b * Tt + row0) * 256 + colb + dn * 8;
        size_t off1 = ((size_t)b * Tt + row0 + 8) * 256 + colb + dn * 8;
        uint32_t hi, lo;
        split_pack2(o[dn][0] * i0, o[dn][1] * i0, hi, lo);
        *(uint32_t*)(yh + off0) = hi;
        *(uint32_t*)(yl + off0) = lo;
        split_pack2(o[dn][2] * i1, o[dn][3] * i1, hi, lo);
        *(uint32_t*)(yh + off1) = hi;
        *(uint32_t*)(yl + off1) = lo;
    }
}

// ===================== launcher ==============================================
extern "C" void kernel_launch(void* const* d_in, const int* in_sizes, int n_in,
                              void* d_out, int out_size)
{
    const float* x  = (const float*)d_in[0];
    const float* Wq = (const float*)d_in[1];
    const float* Wk = (const float*)d_in[2];
    const float* Wv = (const float*)d_in[3];
    const float* Wo = (const float*)d_in[4];
    float* out = (float*)d_out;

    float *cosp, *sinp;
    bf16 *xh, *xl, *yhp, *ylp;
    bf16 *wqh, *wql, *woh, *wol;
    bf16 *qhp, *qlp, *khp, *klp, *vhp, *vlp;
    cudaGetSymbolAddress((void**)&cosp, g_cos);
    cudaGetSymbolAddress((void**)&sinp, g_sin);
    cudaGetSymbolAddress((void**)&xh, g_xh);
    cudaGetSymbolAddress((void**)&xl, g_xl);
    cudaGetSymbolAddress((void**)&yhp, g_yh);
    cudaGetSymbolAddress((void**)&ylp, g_yl);
    cudaGetSymbolAddress((void**)&wqh, g_wqkv_hi);
    cudaGetSymbolAddress((void**)&wql, g_wqkv_lo);
    cudaGetSymbolAddress((void**)&woh, g_wo_hi);
    cudaGetSymbolAddress((void**)&wol, g_wo_lo);
    cudaGetSymbolAddress((void**)&qhp, g_qh);
    cudaGetSymbolAddress((void**)&qlp, g_ql);
    cudaGetSymbolAddress((void**)&khp, g_kh);
    cudaGetSymbolAddress((void**)&klp, g_kl);
    cudaGetSymbolAddress((void**)&vhp, g_vh);
    cudaGetSymbolAddress((void**)&vlp, g_vl);

    const int M = Bb * Tt;                 // 49152
    const int gemm_smem = 69632;           // max(2 stages 64K, C bounce 69632)
    const int attn_smem = 98304;           // Q 32K + 2 KV stages 64K

    cudaFuncSetAttribute(gemm_mma_kernel,
                         cudaFuncAttributeMaxDynamicSharedMemorySize, gemm_smem);
    cudaFuncSetAttribute(attn_mma_kernel,
                         cudaFuncAttributeMaxDynamicSharedMemorySize, attn_smem);

    // 1. split x to bf16 hi/lo ; weight pack/split + rope tables
    split_x_kernel<<<12288, 256>>>((const float4*)x, (uint2*)xh, (uint2*)xl);
    prep_kernel<<<816, 256>>>(Wq, Wk, Wv, Wo);

    // 2. fused QKV projection + RoPE + split epilogue (Ntot = 512)
    gemm_mma_kernel<<<dim3(4, M / 128), 256, gemm_smem>>>(
        xh, xl, wqh, wql, nullptr,
        qhp, qlp, khp, klp, vhp, vlp, cosp, sinp, 1);

    // 3. HMMA flash attention (writes y split)
    attn_mma_kernel<<<dim3(Tt / 128, Hh, Bb), 256, attn_smem>>>(
        qhp, qlp, khp, klp, vhp, vlp, yhp, ylp);

    // 4. output projection (Ntot = 256)
    gemm_mma_kernel<<<dim3(2, M / 128), 256, gemm_smem>>>(
        yhp, ylp, woh, wol, out,
        nullptr, nullptr, nullptr, nullptr, nullptr, nullptr,
        nullptr, nullptr, 0);
}

// round 15
// speedup vs baseline: 2.9705x; 1.0946x over previous
#include <cuda_runtime.h>
#include <cuda_bf16.h>
#include <cstdint>
#include <math.h>

#define Bb   128
#define Tt   384
#define Cc   256
#define Hh   4
#define KVh  2
#define Dd   64
#define REPr 2

typedef __nv_bfloat16 bf16;

// ===================== scratch (static device globals) =======================
__device__ __align__(16) bf16 g_xh[(size_t)Bb * Tt * Cc];
__device__ __align__(16) bf16 g_xl[(size_t)Bb * Tt * Cc];
__device__ __align__(16) bf16 g_yh[(size_t)Bb * Tt * Cc];
__device__ __align__(16) bf16 g_yl[(size_t)Bb * Tt * Cc];
__device__ __align__(16) bf16 g_qh[(size_t)Bb * Hh * Tt * Dd];
__device__ __align__(16) bf16 g_ql[(size_t)Bb * Hh * Tt * Dd];
__device__ __align__(16) bf16 g_kh[(size_t)Bb * KVh * Tt * Dd];
__device__ __align__(16) bf16 g_kl[(size_t)Bb * KVh * Tt * Dd];
__device__ __align__(16) bf16 g_vh[(size_t)Bb * KVh * Tt * Dd];
__device__ __align__(16) bf16 g_vl[(size_t)Bb * KVh * Tt * Dd];
__device__ __align__(16) bf16 g_wqkv_hi[512 * 256];
__device__ __align__(16) bf16 g_wqkv_lo[512 * 256];
__device__ __align__(16) bf16 g_wo_hi[256 * 256];
__device__ __align__(16) bf16 g_wo_lo[256 * 256];
__device__ __align__(16) float g_cos[Tt * 32];
__device__ __align__(16) float g_sin[Tt * 32];

// ===================== small helpers ========================================
__device__ __forceinline__ uint32_t smem_to_u32(const void* p) {
    uint32_t a;
    asm("{ .reg .u64 t; cvta.to.shared.u64 t, %1; cvt.u32.u64 %0, t; }"
        : "=r"(a) : "l"(p));
    return a;
}

// XOR-16B swizzle for 128B rows: conflict-free ldmatrix
__device__ __forceinline__ uint32_t swz(int row, int col_bytes) {
    return (uint32_t)(row * 128 + (((col_bytes >> 4) ^ (row & 7)) << 4) +
                      (col_bytes & 15));
}

__device__ __forceinline__ void split_pack2(float a, float b,
                                            uint32_t& hi, uint32_t& lo)
{
    bf16 ha = __float2bfloat16(a);
    bf16 hb = __float2bfloat16(b);
    bf16 la = __float2bfloat16(a - __bfloat162float(ha));
    bf16 lb = __float2bfloat16(b - __bfloat162float(hb));
    hi = ((uint32_t)__bfloat16_as_ushort(hb) << 16) | __bfloat16_as_ushort(ha);
    lo = ((uint32_t)__bfloat16_as_ushort(lb) << 16) | __bfloat16_as_ushort(la);
}

#define LDSM_X4(r0, r1, r2, r3, addr) \
    asm volatile("ldmatrix.sync.aligned.m8n8.x4.shared.b16 {%0,%1,%2,%3}, [%4];" \
        : "=r"(r0), "=r"(r1), "=r"(r2), "=r"(r3) : "r"(addr))

#define LDSM_X4_T(r0, r1, r2, r3, addr) \
    asm volatile("ldmatrix.sync.aligned.m8n8.x4.trans.shared.b16 {%0,%1,%2,%3}, [%4];" \
        : "=r"(r0), "=r"(r1), "=r"(r2), "=r"(r3) : "r"(addr))

#define MMA_BF16(c, a, b0, b1) \
    asm volatile("mma.sync.aligned.m16n8k16.row.col.f32.bf16.bf16.f32 " \
        "{%0,%1,%2,%3}, {%4,%5,%6,%7}, {%8,%9}, {%0,%1,%2,%3};" \
        : "+f"((c)[0]), "+f"((c)[1]), "+f"((c)[2]), "+f"((c)[3]) \
        : "r"((a)[0]), "r"((a)[1]), "r"((a)[2]), "r"((a)[3]), \
          "r"(b0), "r"(b1))

#define CP16(dst, src) \
    asm volatile("cp.async.cg.shared.global [%0], [%1], 16;" \
        :: "r"(dst), "l"(src) : "memory")
#define CP_COMMIT() asm volatile("cp.async.commit_group;" ::: "memory")
#define CP_WAIT1()  asm volatile("cp.async.wait_group 1;" ::: "memory")
#define CP_WAIT0()  asm volatile("cp.async.wait_group 0;" ::: "memory")

// ===================== split x into bf16 hi/lo ===============================
__global__ void split_x_kernel(const float4* __restrict__ x4,
                               uint2* __restrict__ xh2,
                               uint2* __restrict__ xl2)
{
    size_t i = (size_t)blockIdx.x * 256 + threadIdx.x;
    float4 f = x4[i];
    uint32_t h01, l01, h23, l23;
    split_pack2(f.x, f.y, h01, l01);
    split_pack2(f.z, f.w, h23, l23);
    xh2[i] = make_uint2(h01, h23);
    xl2[i] = make_uint2(l01, l23);
}

// ===================== prep: weight transpose/pack/split + rope tables ======
__global__ void prep_kernel(const float* __restrict__ Wq,
                            const float* __restrict__ Wk,
                            const float* __restrict__ Wv,
                            const float* __restrict__ Wo)
{
    int idx = blockIdx.x * 256 + threadIdx.x;
    if (idx < 131072) {
        int n = idx >> 8, k = idx & 255;
        float v;
        if (n < 256)      v = Wq[k * 256 + n];
        else if (n < 384) v = Wk[k * 128 + (n - 256)];
        else              v = Wv[k * 128 + (n - 384)];
        bf16 h = __float2bfloat16(v);
        g_wqkv_hi[idx] = h;
        g_wqkv_lo[idx] = __float2bfloat16(v - __bfloat162float(h));
    } else if (idx < 131072 + 65536) {
        int j = idx - 131072;
        int n = j >> 8, k = j & 255;
        float v = Wo[k * 256 + n];
        bf16 h = __float2bfloat16(v);
        g_wo_hi[j] = h;
        g_wo_lo[j] = __float2bfloat16(v - __bfloat162float(h));
    } else if (idx < 131072 + 65536 + Tt * 32) {
        int j = idx - 196608;
        int t = j >> 5, i = j & 31;
        float inv = exp2f(-(float)i * (2.0f / 64.0f) * 13.287712379549449f);
        float ang = (float)t * inv;
        g_cos[j] = cosf(ang);
        g_sin[j] = sinf(ang);
    }
}

// ===================== HMMA GEMM, cp.async 2-stage pipeline ==================
// C[M,Ntot] = (Ah+Al)[M,256] @ (Bh+Bl)^T, pre-split bf16. CTA 128x128.
// K in 8 chunks of 32; smem row = 128B = [hi 64B | lo 64B], swizzled.
// Stage = 32KB (A 16K + B 16K); 2 stages. 8 warps 2(m) x 4(n).
// mode 0: fp32 out.  mode 1: QKV epilogue -> rope + split bf16 hi/lo q/k/v.
__global__ __launch_bounds__(256, 2)
void gemm_mma_kernel(const bf16* __restrict__ Ah, const bf16* __restrict__ Al,
                     const bf16* __restrict__ Bh, const bf16* __restrict__ Bl,
                     float* __restrict__ outp,
                     bf16* __restrict__ qh, bf16* __restrict__ ql,
                     bf16* __restrict__ kh, bf16* __restrict__ kl,
                     bf16* __restrict__ vh, bf16* __restrict__ vl,
                     const float* __restrict__ ctab,
                     const float* __restrict__ stab,
                     int mode)
{
    extern __shared__ char smem[];
    uint32_t sb = smem_to_u32(smem);
    const uint32_t SS = 32768;

    int tid  = threadIdx.x;
    int wid  = tid >> 5, lane = tid & 31;
    int wm   = wid & 1;
    int wn   = wid >> 1;
    int m0   = blockIdx.y * 128;
    int n0   = blockIdx.x * 128;

    float acc[4][4][4];
    #pragma unroll
    for (int i = 0; i < 4; i++)
        #pragma unroll
        for (int j = 0; j < 4; j++)
            #pragma unroll
            for (int e = 0; e < 4; e++) acc[i][j][e] = 0.f;

    int lrow = tid >> 1, hf = tid & 1;
    const bf16* gAh = Ah + (size_t)(m0 + lrow) * 256 + hf * 16;
    const bf16* gAl = Al + (size_t)(m0 + lrow) * 256 + hf * 16;
    const bf16* gBh = Bh + (size_t)(n0 + lrow) * 256 + hf * 16;
    const bf16* gBl = Bl + (size_t)(n0 + lrow) * 256 + hf * 16;
    uint32_t dH0 = swz(lrow, hf * 32);
    uint32_t dH1 = swz(lrow, hf * 32 + 16);
    uint32_t dL0 = swz(lrow, 64 + hf * 32);
    uint32_t dL1 = swz(lrow, 64 + hf * 32 + 16);

    auto issue = [&](int c, int s) {
        uint32_t ab = sb + (uint32_t)s * SS;
        uint32_t bb = ab + 16384;
        const bf16* a0 = gAh + c * 32;
        const bf16* a1 = gAl + c * 32;
        const bf16* b0 = gBh + c * 32;
        const bf16* b1 = gBl + c * 32;
        CP16(ab + dH0, a0); CP16(ab + dH1, a0 + 8);
        CP16(ab + dL0, a1); CP16(ab + dL1, a1 + 8);
        CP16(bb + dH0, b0); CP16(bb + dH1, b0 + 8);
        CP16(bb + dL0, b1); CP16(bb + dL1, b1 + 8);
        CP_COMMIT();
    };

    auto compute = [&](int s) {
        uint32_t ab = sb + (uint32_t)s * SS;
        uint32_t bb = ab + 16384;
        #pragma unroll
        for (int ks = 0; ks < 2; ks++) {
            int ar  = wm * 64 + (lane & 15);
            int ach = (ks * 16 + ((lane >> 4) << 3)) * 2;
            int br  = wn * 32 + (lane & 7) + ((lane >> 4) << 3);
            int bch = (ks * 16 + (((lane >> 3) & 1) << 3)) * 2;

            uint32_t rbh[8], rbl[8], ra[4][4];
            #pragma unroll
            for (int g = 0; g < 2; g++) {
                LDSM_X4(rbh[g*4+0], rbh[g*4+1], rbh[g*4+2], rbh[g*4+3],
                        bb + swz(br + g * 16, bch));
                LDSM_X4(rbl[g*4+0], rbl[g*4+1], rbl[g*4+2], rbl[g*4+3],
                        bb + swz(br + g * 16, 64 + bch));
            }
            #pragma unroll
            for (int i = 0; i < 4; i++)
                LDSM_X4(ra[i][0], ra[i][1], ra[i][2], ra[i][3],
                        ab + swz(ar + i * 16, ach));
            #pragma unroll
            for (int i = 0; i < 4; i++)
                #pragma unroll
                for (int j = 0; j < 4; j++) {
                    int g = j >> 1, p = (j & 1) * 2;
                    MMA_BF16(acc[i][j], ra[i], rbh[g*4+p], rbh[g*4+p+1]);
                    MMA_BF16(acc[i][j], ra[i], rbl[g*4+p], rbl[g*4+p+1]);
                }
            #pragma unroll
            for (int i = 0; i < 4; i++)
                LDSM_X4(ra[i][0], ra[i][1], ra[i][2], ra[i][3],
                        ab + swz(ar + i * 16, 64 + ach));
            #pragma unroll
            for (int i = 0; i < 4; i++)
                #pragma unroll
                for (int j = 0; j < 4; j++) {
                    int g = j >> 1, p = (j & 1) * 2;
                    MMA_BF16(acc[i][j], ra[i], rbh[g*4+p], rbh[g*4+p+1]);
                }
        }
    };

    issue(0, 0);
    #pragma unroll 1
    for (int c = 0; c < 8; c++) {
        if (c < 7) { issue(c + 1, (c + 1) & 1); CP_WAIT1(); }
        else       { CP_WAIT0(); }
        __syncthreads();
        compute(c & 1);
        __syncthreads();
    }

    // ---- C to smem bounce (stride 136 floats) ----
    float* Csm = (float*)smem;
    #pragma unroll
    for (int i = 0; i < 4; i++)
        #pragma unroll
        for (int j = 0; j < 4; j++) {
            int row = wm * 64 + i * 16 + (lane >> 2);
            int col = wn * 32 + j * 8 + (lane & 3) * 2;
            *(float2*)&Csm[(size_t)row * 136 + col] =
                make_float2(acc[i][j][0], acc[i][j][1]);
            *(float2*)&Csm[(size_t)(row + 8) * 136 + col] =
                make_float2(acc[i][j][2], acc[i][j][3]);
        }
    __syncthreads();

    int r    = tid >> 1;
    int half = tid & 1;
    int m    = m0 + r;
    const float* csrc = Csm + (size_t)r * 136 + half * 64;

    if (mode == 0) {
        float* dst = outp + (size_t)m * 256 + n0 + half * 64;
        #pragma unroll
        for (int j = 0; j < 16; j++)
            *(float4*)(dst + 4 * j) = *(const float4*)(csrc + 4 * j);
    } else {
        int b = m / Tt, t = m % Tt;
        int g = (n0 >> 6) + half;   // 0..3 Q heads, 4..5 K kv, 6..7 V kv
        float vals[64];
        if (g < 6) {
            #pragma unroll
            for (int i = 0; i < 32; i++) {
                float cs = ctab[t * 32 + i], sn = stab[t * 32 + i];
                float x0 = csrc[i], x1 = csrc[32 + i];
                vals[i]      = x0 * cs - x1 * sn;
                vals[i + 32] = x1 * cs + x0 * sn;
            }
            if (g < 4) {
                #pragma unroll
                for (int i = 0; i < 64; i++) vals[i] *= 0.125f;   // 1/sqrt(D)
            }
        } else {
            #pragma unroll
            for (int i = 0; i < 64; i++) vals[i] = csrc[i];
        }
        uint32_t hw[32], lw[32];
        #pragma unroll
        for (int jj = 0; jj < 32; jj++)
            split_pack2(vals[2 * jj], vals[2 * jj + 1], hw[jj], lw[jj]);

        size_t idx;
        bf16 *dh, *dl;
        if (g < 4)      { idx = (((size_t)b * Hh  + g      ) * Tt + t) * 64; dh = qh; dl = ql; }
        else if (g < 6) { idx = (((size_t)b * KVh + (g - 4)) * Tt + t) * 64; dh = kh; dl = kl; }
        else            { idx = (((size_t)b * KVh + (g - 6)) * Tt + t) * 64; dh = vh; dl = vl; }
        uint4* dh4 = (uint4*)(dh + idx);
        uint4* dl4 = (uint4*)(dl + idx);
        #pragma unroll
        for (int u = 0; u < 8; u++) {
            dh4[u] = make_uint4(hw[4*u], hw[4*u+1], hw[4*u+2], hw[4*u+3]);
            dl4[u] = make_uint4(lw[4*u], lw[4*u+1], lw[4*u+2], lw[4*u+3]);
        }
    }
}

// ===================== HMMA causal GQA flash attention (occ-2 layout) ========
// grid (T/128, H, B), 256 threads. Warp w owns q rows [w*16, w*16+16).
// smem (80KB, 2 CTAs/SM): Qlo 16KB | KV stage0 32KB | KV stage1 32KB.
// Q-hi is staged through stage1, fragments extracted, then stage1 reused.
// Q-lo fragments reloaded from smem per tile (keeps regs <= 128).
__global__ __launch_bounds__(256, 2)
void attn_mma_kernel(const bf16* __restrict__ qh, const bf16* __restrict__ ql,
                     const bf16* __restrict__ kh, const bf16* __restrict__ kl,
                     const bf16* __restrict__ vh, const bf16* __restrict__ vl,
                     bf16* __restrict__ yh, bf16* __restrict__ yl)
{
    extern __shared__ char smem[];
    uint32_t ub  = smem_to_u32(smem);
    uint32_t uQl = ub;                       // 16KB persistent Q-lo

    int tid  = threadIdx.x;
    int w    = tid >> 5, lane = tid & 31;
    int q0   = blockIdx.x * 128;
    int h    = blockIdx.y;
    int b    = blockIdx.z;
    int kvh  = h >> 1;

    size_t kvbase = ((size_t)b * KVh + kvh) * Tt * 64;
    int ntiles = q0 / 64 + 2;

    // cp.async KV mapping: 4 threads per row
    int krow = tid >> 2, part = tid & 3;
    const bf16* gK0 = kh + kvbase + (size_t)krow * 64 + part * 16;
    const bf16* gK1 = kl + kvbase + (size_t)krow * 64 + part * 16;
    const bf16* gV0 = vh + kvbase + (size_t)krow * 64 + part * 16;
    const bf16* gV1 = vl + kvbase + (size_t)krow * 64 + part * 16;
    uint32_t d0 = swz(krow, part * 32);
    uint32_t d1 = swz(krow, part * 32 + 16);

    auto issueKV = [&](int kt, int s) {
        uint32_t base = ub + 16384 + (uint32_t)s * 32768;
        size_t off = (size_t)kt * 4096;
        CP16(base         + d0, gK0 + off); CP16(base         + d1, gK0 + off + 8);
        CP16(base +  8192 + d0, gK1 + off); CP16(base +  8192 + d1, gK1 + off + 8);
        CP16(base + 16384 + d0, gV0 + off); CP16(base + 16384 + d1, gV0 + off + 8);
        CP16(base + 24576 + d0, gV1 + off); CP16(base + 24576 + d1, gV1 + off + 8);
        CP_COMMIT();
    };

    // ---- stage Q: hi -> stage1 region (transient), lo -> persistent uQl ----
    {
        int row = tid >> 1, hf2 = tid & 1;
        size_t src = (((size_t)b * Hh + h) * Tt + q0 + row) * 64 + hf2 * 32;
        const uint4* s0 = (const uint4*)(qh + src);
        const uint4* s1 = (const uint4*)(ql + src);
        #pragma unroll
        for (int j = 0; j < 4; j++) {
            uint32_t off = swz(row, hf2 * 64 + j * 16);
            *(uint4*)(smem + 16384 + 32768 + off) = s0[j];   // Q-hi in stage1
            *(uint4*)(smem + off)                 = s1[j];   // Q-lo persistent
        }
    }
    issueKV(0, 0);     // prefetch KV tile 0 into stage0
    __syncthreads();

    // ---- Q-hi fragments (persist in regs); then release stage1 ----
    int qar = w * 16 + (lane & 15);
    int qac_base = ((lane >> 4) << 3) * 2;
    uint32_t qfh[4][4];
    #pragma unroll
    for (int ks = 0; ks < 4; ks++)
        LDSM_X4(qfh[ks][0], qfh[ks][1], qfh[ks][2], qfh[ks][3],
                ub + 16384 + 32768 + swz(qar, ks * 32 + qac_base));
    __syncthreads();   // all warps done reading Q-hi before tile1 overwrites

    float o[8][4];
    #pragma unroll
    for (int i = 0; i < 8; i++)
        #pragma unroll
        for (int e = 0; e < 4; e++) o[i][e] = 0.f;
    float m0v = -1e30f, m1v = -1e30f, l0v = 0.f, l1v = 0.f;

    int warp_max_row = q0 + w * 16 + 15;

    #pragma unroll 1
    for (int kt = 0; kt < ntiles; kt++) {
        if (kt + 1 < ntiles) { issueKV(kt + 1, (kt + 1) & 1); CP_WAIT1(); }
        else                 { CP_WAIT0(); }
        __syncthreads();

        if (kt * 64 <= warp_max_row) {
            uint32_t kb = ub + 16384 + (uint32_t)(kt & 1) * 32768;
            uint32_t uKh = kb, uKl = kb + 8192, uVh = kb + 16384, uVl = kb + 24576;

            // reload Q-lo fragments (per tile, keeps them out of the PV phase)
            uint32_t qfl[4][4];
            #pragma unroll
            for (int ks = 0; ks < 4; ks++)
                LDSM_X4(qfl[ks][0], qfl[ks][1], qfl[ks][2], qfl[ks][3],
                        uQl + swz(qar, ks * 32 + qac_base));

            // ---- S = Q @ K^T (bf16x3), K fragments streamed per-nf ----
            float s[8][4];
            #pragma unroll
            for (int j = 0; j < 8; j++)
                #pragma unroll
                for (int e = 0; e < 4; e++) s[j][e] = 0.f;

            int br = (lane & 7) + ((lane >> 4) << 3);
            #pragma unroll
            for (int ks = 0; ks < 4; ks++) {
                int bc = (ks * 16 + (((lane >> 3) & 1) << 3)) * 2;
                #pragma unroll
                for (int nf = 0; nf < 4; nf++) {
                    uint32_t kbh[4], kbl[4];
                    LDSM_X4(kbh[0], kbh[1], kbh[2], kbh[3],
                            uKh + swz(nf * 16 + br, bc));
                    LDSM_X4(kbl[0], kbl[1], kbl[2], kbl[3],
                            uKl + swz(nf * 16 + br, bc));
                    #pragma unroll
                    for (int p = 0; p < 2; p++) {
                        int j = nf * 2 + p;
                        MMA_BF16(s[j], qfh[ks], kbh[2*p], kbh[2*p+1]);
                        MMA_BF16(s[j], qfl[ks], kbh[2*p], kbh[2*p+1]);
                        MMA_BF16(s[j], qfh[ks], kbl[2*p], kbl[2*p+1]);
                    }
                }
            }

            // ---- causal mask ----
            int rowg = q0 + w * 16 + (lane >> 2);
            #pragma unroll
            for (int j = 0; j < 8; j++) {
                int colg = kt * 64 + j * 8 + 2 * (lane & 3);
                if (colg     > rowg)     s[j][0] = -1e30f;
                if (colg + 1 > rowg)     s[j][1] = -1e30f;
                if (colg     > rowg + 8) s[j][2] = -1e30f;
                if (colg + 1 > rowg + 8) s[j][3] = -1e30f;
            }

            // ---- online softmax (quad-shuffle row stats) ----
            float t0 = -1e30f, t1 = -1e30f;
            #pragma unroll
            for (int j = 0; j < 8; j++) {
                t0 = fmaxf(t0, fmaxf(s[j][0], s[j][1]));
                t1 = fmaxf(t1, fmaxf(s[j][2], s[j][3]));
            }
            t0 = fmaxf(t0, __shfl_xor_sync(0xffffffffu, t0, 1));
            t0 = fmaxf(t0, __shfl_xor_sync(0xffffffffu, t0, 2));
            t1 = fmaxf(t1, __shfl_xor_sync(0xffffffffu, t1, 1));
            t1 = fmaxf(t1, __shfl_xor_sync(0xffffffffu, t1, 2));
            float mn0 = fmaxf(m0v, t0), mn1 = fmaxf(m1v, t1);
            float f0 = __expf(m0v - mn0), f1 = __expf(m1v - mn1);
            m0v = mn0; m1v = mn1;

            float ps0 = 0.f, ps1 = 0.f;
            #pragma unroll
            for (int j = 0; j < 8; j++) {
                s[j][0] = __expf(s[j][0] - mn0); ps0 += s[j][0];
                s[j][1] = __expf(s[j][1] - mn0); ps0 += s[j][1];
                s[j][2] = __expf(s[j][2] - mn1); ps1 += s[j][2];
                s[j][3] = __expf(s[j][3] - mn1); ps1 += s[j][3];
            }
            ps0 += __shfl_xor_sync(0xffffffffu, ps0, 1);
            ps0 += __shfl_xor_sync(0xffffffffu, ps0, 2);
            ps1 += __shfl_xor_sync(0xffffffffu, ps1, 1);
            ps1 += __shfl_xor_sync(0xffffffffu, ps1, 2);
            l0v = l0v * f0 + ps0;
            l1v = l1v * f1 + ps1;

            #pragma unroll
            for (int dn = 0; dn < 8; dn++) {
                o[dn][0] *= f0; o[dn][1] *= f0;
                o[dn][2] *= f1; o[dn][3] *= f1;
            }

            // ---- P fragments (accumulator -> A-frag identity, hi/lo) ----
            uint32_t pah[4][4], pal[4][4];
            #pragma unroll
            for (int kc = 0; kc < 4; kc++) {
                split_pack2(s[2*kc][0],   s[2*kc][1],   pah[kc][0], pal[kc][0]);
                split_pack2(s[2*kc][2],   s[2*kc][3],   pah[kc][1], pal[kc][1]);
                split_pack2(s[2*kc+1][0], s[2*kc+1][1], pah[kc][2], pal[kc][2]);
                split_pack2(s[2*kc+1][2], s[2*kc+1][3], pah[kc][3], pal[kc][3]);
            }

            // ---- O += P @ V (bf16x3), V frags streamed via ldmatrix.trans ----
            #pragma unroll
            for (int kc = 0; kc < 4; kc++) {
                int vr = kc * 16 + (lane & 7) + ((lane >> 3) & 1) * 8;
                #pragma unroll
                for (int dn2 = 0; dn2 < 4; dn2++) {
                    int vc = (dn2 * 16 + (lane >> 4) * 8) * 2;
                    uint32_t vbh[4], vbl[4];
                    LDSM_X4_T(vbh[0], vbh[1], vbh[2], vbh[3], uVh + swz(vr, vc));
                    LDSM_X4_T(vbl[0], vbl[1], vbl[2], vbl[3], uVl + swz(vr, vc));
                    #pragma unroll
                    for (int p = 0; p < 2; p++) {
                        int dn = dn2 * 2 + p;
                        MMA_BF16(o[dn], pah[kc], vbh[2*p], vbh[2*p+1]);
                        MMA_BF16(o[dn], pal[kc], vbh[2*p], vbh[2*p+1]);
                        MMA_BF16(o[dn], pah[kc], vbl[2*p], vbl[2*p+1]);
                    }
                }
            }
        }
        __syncthreads();
    }

    // ---- epilogue: y split bf16 hi/lo, layout [B,T,H*D] ----
    float i0 = 1.f / l0v, i1 = 1.f / l1v;
    int row0 = q0 + w * 16 + (lane >> 2);
    int colb = h * 64 + 2 * (lane & 3);
    #pragma unroll
    for (int dn = 0; dn < 8; dn++) {
        size_t off0 = ((size_t)b * Tt + row0) * 256 + colb + dn * 8;
        size_t off1 = ((size_t)b * Tt + row0 + 8) * 256 + colb + dn * 8;
        uint32_t hi, lo;
        split_pack2(o[dn][0] * i0, o[dn][1] * i0, hi, lo);
        *(uint32_t*)(yh + off0) = hi;
        *(uint32_t*)(yl + off0) = lo;
        split_pack2(o[dn][2] * i1, o[dn][3] * i1, hi, lo);
        *(uint32_t*)(yh + off1) = hi;
        *(uint32_t*)(yl + off1) = lo;
    }
}

// ===================== launcher ==============================================
extern "C" void kernel_launch(void* const* d_in, const int* in_sizes, int n_in,
                              void* d_out, int out_size)
{
    const float* x  = (const float*)d_in[0];
    const float* Wq = (const float*)d_in[1];
    const float* Wk = (const float*)d_in[2];
    const float* Wv = (const float*)d_in[3];
    const float* Wo = (const float*)d_in[4];
    float* out = (float*)d_out;

    float *cosp, *sinp;
    bf16 *xh, *xl, *yhp, *ylp;
    bf16 *wqh, *wql, *woh, *wol;
    bf16 *qhp, *qlp, *khp, *klp, *vhp, *vlp;
    cudaGetSymbolAddress((void**)&cosp, g_cos);
    cudaGetSymbolAddress((void**)&sinp, g_sin);
    cudaGetSymbolAddress((void**)&xh, g_xh);
    cudaGetSymbolAddress((void**)&xl, g_xl);
    cudaGetSymbolAddress((void**)&yhp, g_yh);
    cudaGetSymbolAddress((void**)&ylp, g_yl);
    cudaGetSymbolAddress((void**)&wqh, g_wqkv_hi);
    cudaGetSymbolAddress((void**)&wql, g_wqkv_lo);
    cudaGetSymbolAddress((void**)&woh, g_wo_hi);
    cudaGetSymbolAddress((void**)&wol, g_wo_lo);
    cudaGetSymbolAddress((void**)&qhp, g_qh);
    cudaGetSymbolAddress((void**)&qlp, g_ql);
    cudaGetSymbolAddress((void**)&khp, g_kh);
    cudaGetSymbolAddress((void**)&klp, g_kl);
    cudaGetSymbolAddress((void**)&vhp, g_vh);
    cudaGetSymbolAddress((void**)&vlp, g_vl);

    const int M = Bb * Tt;                 // 49152
    const int gemm_smem = 69632;           // max(2 stages 64K, C bounce 69632)
    const int attn_smem = 81920;           // Qlo 16K + 2 KV stages 64K

    cudaFuncSetAttribute(gemm_mma_kernel,
                         cudaFuncAttributeMaxDynamicSharedMemorySize, gemm_smem);
    cudaFuncSetAttribute(attn_mma_kernel,
                         cudaFuncAttributeMaxDynamicSharedMemorySize, attn_smem);

    // 1. split x to bf16 hi/lo ; weight pack/split + rope tables
    split_x_kernel<<<12288, 256>>>((const float4*)x, (uint2*)xh, (uint2*)xl);
    prep_kernel<<<816, 256>>>(Wq, Wk, Wv, Wo);

    // 2. fused QKV projection + RoPE + split epilogue (Ntot = 512)
    gemm_mma_kernel<<<dim3(4, M / 128), 256, gemm_smem>>>(
        xh, xl, wqh, wql, nullptr,
        qhp, qlp, khp, klp, vhp, vlp, cosp, sinp, 1);

    // 3. HMMA flash attention (writes y split)
    attn_mma_kernel<<<dim3(Tt / 128, Hh, Bb), 256, attn_smem>>>(
        qhp, qlp, khp, klp, vhp, vlp, yhp, ylp);

    // 4. output projection (Ntot = 256)
    gemm_mma_kernel<<<dim3(2, M / 128), 256, gemm_smem>>>(
        yhp, ylp, woh, wol, out,
        nullptr, nullptr, nullptr, nullptr, nullptr, nullptr,
        nullptr, nullptr, 0);
}

// round 16
// speedup vs baseline: 3.0159x; 1.0153x over previous
#include <cuda_runtime.h>
#include <cuda_bf16.h>
#include <cstdint>
#include <math.h>

#define Bb   128
#define Tt   384
#define Cc   256
#define Hh   4
#define KVh  2
#define Dd   64
#define REPr 2

typedef __nv_bfloat16 bf16;

// ===================== scratch (static device globals) =======================
__device__ __align__(16) bf16 g_xh[(size_t)Bb * Tt * Cc];
__device__ __align__(16) bf16 g_xl[(size_t)Bb * Tt * Cc];
__device__ __align__(16) bf16 g_yh[(size_t)Bb * Tt * Cc];
__device__ __align__(16) bf16 g_yl[(size_t)Bb * Tt * Cc];
__device__ __align__(16) bf16 g_qh[(size_t)Bb * Hh * Tt * Dd];
__device__ __align__(16) bf16 g_ql[(size_t)Bb * Hh * Tt * Dd];
__device__ __align__(16) bf16 g_kh[(size_t)Bb * KVh * Tt * Dd];
__device__ __align__(16) bf16 g_kl[(size_t)Bb * KVh * Tt * Dd];
__device__ __align__(16) bf16 g_vh[(size_t)Bb * KVh * Tt * Dd];
__device__ __align__(16) bf16 g_vl[(size_t)Bb * KVh * Tt * Dd];
__device__ __align__(16) bf16 g_wqkv_hi[512 * 256];
__device__ __align__(16) bf16 g_wqkv_lo[512 * 256];
__device__ __align__(16) bf16 g_wo_hi[256 * 256];
__device__ __align__(16) bf16 g_wo_lo[256 * 256];
__device__ __align__(16) float g_cos[Tt * 32];
__device__ __align__(16) float g_sin[Tt * 32];

// ===================== small helpers ========================================
__device__ __forceinline__ uint32_t smem_to_u32(const void* p) {
    uint32_t a;
    asm("{ .reg .u64 t; cvta.to.shared.u64 t, %1; cvt.u32.u64 %0, t; }"
        : "=r"(a) : "l"(p));
    return a;
}

// XOR-16B swizzle for 128B rows: conflict-free ldmatrix
__device__ __forceinline__ uint32_t swz(int row, int col_bytes) {
    return (uint32_t)(row * 128 + (((col_bytes >> 4) ^ (row & 7)) << 4) +
                      (col_bytes & 15));
}

__device__ __forceinline__ void split_pack2(float a, float b,
                                            uint32_t& hi, uint32_t& lo)
{
    bf16 ha = __float2bfloat16(a);
    bf16 hb = __float2bfloat16(b);
    bf16 la = __float2bfloat16(a - __bfloat162float(ha));
    bf16 lb = __float2bfloat16(b - __bfloat162float(hb));
    hi = ((uint32_t)__bfloat16_as_ushort(hb) << 16) | __bfloat16_as_ushort(ha);
    lo = ((uint32_t)__bfloat16_as_ushort(lb) << 16) | __bfloat16_as_ushort(la);
}

#define LDSM_X4(r0, r1, r2, r3, addr) \
    asm volatile("ldmatrix.sync.aligned.m8n8.x4.shared.b16 {%0,%1,%2,%3}, [%4];" \
        : "=r"(r0), "=r"(r1), "=r"(r2), "=r"(r3) : "r"(addr))

#define LDSM_X4_T(r0, r1, r2, r3, addr) \
    asm volatile("ldmatrix.sync.aligned.m8n8.x4.trans.shared.b16 {%0,%1,%2,%3}, [%4];" \
        : "=r"(r0), "=r"(r1), "=r"(r2), "=r"(r3) : "r"(addr))

#define MMA_BF16(c, a, b0, b1) \
    asm volatile("mma.sync.aligned.m16n8k16.row.col.f32.bf16.bf16.f32 " \
        "{%0,%1,%2,%3}, {%4,%5,%6,%7}, {%8,%9}, {%0,%1,%2,%3};" \
        : "+f"((c)[0]), "+f"((c)[1]), "+f"((c)[2]), "+f"((c)[3]) \
        : "r"((a)[0]), "r"((a)[1]), "r"((a)[2]), "r"((a)[3]), \
          "r"(b0), "r"(b1))

#define CP16(dst, src) \
    asm volatile("cp.async.cg.shared.global [%0], [%1], 16;" \
        :: "r"(dst), "l"(src) : "memory")
#define CP_COMMIT() asm volatile("cp.async.commit_group;" ::: "memory")
#define CP_WAIT1()  asm volatile("cp.async.wait_group 1;" ::: "memory")
#define CP_WAIT0()  asm volatile("cp.async.wait_group 0;" ::: "memory")

// ===================== split x into bf16 hi/lo ===============================
__global__ void split_x_kernel(const float4* __restrict__ x4,
                               uint2* __restrict__ xh2,
                               uint2* __restrict__ xl2)
{
    size_t i = (size_t)blockIdx.x * 256 + threadIdx.x;
    float4 f = x4[i];
    uint32_t h01, l01, h23, l23;
    split_pack2(f.x, f.y, h01, l01);
    split_pack2(f.z, f.w, h23, l23);
    xh2[i] = make_uint2(h01, h23);
    xl2[i] = make_uint2(l01, l23);
}

// ===================== prep: weight transpose/pack/split + rope tables ======
__global__ void prep_kernel(const float* __restrict__ Wq,
                            const float* __restrict__ Wk,
                            const float* __restrict__ Wv,
                            const float* __restrict__ Wo)
{
    int idx = blockIdx.x * 256 + threadIdx.x;
    if (idx < 131072) {
        int n = idx >> 8, k = idx & 255;
        float v;
        if (n < 256)      v = Wq[k * 256 + n];
        else if (n < 384) v = Wk[k * 128 + (n - 256)];
        else              v = Wv[k * 128 + (n - 384)];
        bf16 h = __float2bfloat16(v);
        g_wqkv_hi[idx] = h;
        g_wqkv_lo[idx] = __float2bfloat16(v - __bfloat162float(h));
    } else if (idx < 131072 + 65536) {
        int j = idx - 131072;
        int n = j >> 8, k = j & 255;
        float v = Wo[k * 256 + n];
        bf16 h = __float2bfloat16(v);
        g_wo_hi[j] = h;
        g_wo_lo[j] = __float2bfloat16(v - __bfloat162float(h));
    } else if (idx < 131072 + 65536 + Tt * 32) {
        int j = idx - 196608;
        int t = j >> 5, i = j & 31;
        float inv = exp2f(-(float)i * (2.0f / 64.0f) * 13.287712379549449f);
        float ang = (float)t * inv;
        g_cos[j] = cosf(ang);
        g_sin[j] = sinf(ang);
    }
}

// ===================== HMMA GEMM, cp.async 3-stage pipeline ==================
// C[M,Ntot] = (Ah+Al)[M,256] @ (Bh+Bl)^T, pre-split bf16. CTA 128x128.
// K in 8 chunks of 32; smem row = 128B = [hi 64B | lo 64B], swizzled.
// Stage = 32KB (A 16K + B 16K); 3 stages, issue 2 ahead, ONE sync per chunk.
// mode 0: fp32 out.  mode 1: QKV epilogue -> rope + split bf16 hi/lo q/k/v.
__global__ __launch_bounds__(256, 2)
void gemm_mma_kernel(const bf16* __restrict__ Ah, const bf16* __restrict__ Al,
                     const bf16* __restrict__ Bh, const bf16* __restrict__ Bl,
                     float* __restrict__ outp,
                     bf16* __restrict__ qh, bf16* __restrict__ ql,
                     bf16* __restrict__ kh, bf16* __restrict__ kl,
                     bf16* __restrict__ vh, bf16* __restrict__ vl,
                     const float* __restrict__ ctab,
                     const float* __restrict__ stab,
                     int mode)
{
    extern __shared__ char smem[];
    uint32_t sb = smem_to_u32(smem);
    const uint32_t SS = 32768;

    int tid  = threadIdx.x;
    int wid  = tid >> 5, lane = tid & 31;
    int wm   = wid & 1;
    int wn   = wid >> 1;
    int m0   = blockIdx.y * 128;
    int n0   = blockIdx.x * 128;

    float acc[4][4][4];
    #pragma unroll
    for (int i = 0; i < 4; i++)
        #pragma unroll
        for (int j = 0; j < 4; j++)
            #pragma unroll
            for (int e = 0; e < 4; e++) acc[i][j][e] = 0.f;

    int lrow = tid >> 1, hf = tid & 1;
    const bf16* gAh = Ah + (size_t)(m0 + lrow) * 256 + hf * 16;
    const bf16* gAl = Al + (size_t)(m0 + lrow) * 256 + hf * 16;
    const bf16* gBh = Bh + (size_t)(n0 + lrow) * 256 + hf * 16;
    const bf16* gBl = Bl + (size_t)(n0 + lrow) * 256 + hf * 16;
    uint32_t dH0 = swz(lrow, hf * 32);
    uint32_t dH1 = swz(lrow, hf * 32 + 16);
    uint32_t dL0 = swz(lrow, 64 + hf * 32);
    uint32_t dL1 = swz(lrow, 64 + hf * 32 + 16);

    auto issue = [&](int c, int s) {
        uint32_t ab = sb + (uint32_t)s * SS;
        uint32_t bb = ab + 16384;
        const bf16* a0 = gAh + c * 32;
        const bf16* a1 = gAl + c * 32;
        const bf16* b0 = gBh + c * 32;
        const bf16* b1 = gBl + c * 32;
        CP16(ab + dH0, a0); CP16(ab + dH1, a0 + 8);
        CP16(ab + dL0, a1); CP16(ab + dL1, a1 + 8);
        CP16(bb + dH0, b0); CP16(bb + dH1, b0 + 8);
        CP16(bb + dL0, b1); CP16(bb + dL1, b1 + 8);
        CP_COMMIT();
    };

    auto compute = [&](int s) {
        uint32_t ab = sb + (uint32_t)s * SS;
        uint32_t bb = ab + 16384;
        #pragma unroll
        for (int ks = 0; ks < 2; ks++) {
            int ar  = wm * 64 + (lane & 15);
            int ach = (ks * 16 + ((lane >> 4) << 3)) * 2;
            int br  = wn * 32 + (lane & 7) + ((lane >> 4) << 3);
            int bch = (ks * 16 + (((lane >> 3) & 1) << 3)) * 2;

            uint32_t rbh[8], rbl[8], ra[4][4];
            #pragma unroll
            for (int g = 0; g < 2; g++) {
                LDSM_X4(rbh[g*4+0], rbh[g*4+1], rbh[g*4+2], rbh[g*4+3],
                        bb + swz(br + g * 16, bch));
                LDSM_X4(rbl[g*4+0], rbl[g*4+1], rbl[g*4+2], rbl[g*4+3],
                        bb + swz(br + g * 16, 64 + bch));
            }
            #pragma unroll
            for (int i = 0; i < 4; i++)
                LDSM_X4(ra[i][0], ra[i][1], ra[i][2], ra[i][3],
                        ab + swz(ar + i * 16, ach));
            #pragma unroll
            for (int i = 0; i < 4; i++)
                #pragma unroll
                for (int j = 0; j < 4; j++) {
                    int g = j >> 1, p = (j & 1) * 2;
                    MMA_BF16(acc[i][j], ra[i], rbh[g*4+p], rbh[g*4+p+1]);
                    MMA_BF16(acc[i][j], ra[i], rbl[g*4+p], rbl[g*4+p+1]);
                }
            #pragma unroll
            for (int i = 0; i < 4; i++)
                LDSM_X4(ra[i][0], ra[i][1], ra[i][2], ra[i][3],
                        ab + swz(ar + i * 16, 64 + ach));
            #pragma unroll
            for (int i = 0; i < 4; i++)
                #pragma unroll
                for (int j = 0; j < 4; j++) {
                    int g = j >> 1, p = (j & 1) * 2;
                    MMA_BF16(acc[i][j], ra[i], rbh[g*4+p], rbh[g*4+p+1]);
                }
        }
    };

    // 3-stage pipeline, one sync per chunk.
    issue(0, 0);
    issue(1, 1);
    #pragma unroll 1
    for (int c = 0; c < 8; c++) {
        if (c < 7) { CP_WAIT1(); } else { CP_WAIT0(); }
        __syncthreads();                   // releases stage (c-1)%3, group c ready
        if (c + 2 < 8) issue(c + 2, (c + 2) % 3);
        compute(c % 3);
    }
    __syncthreads();

    // ---- C to smem bounce (stride 136 floats) ----
    float* Csm = (float*)smem;
    #pragma unroll
    for (int i = 0; i < 4; i++)
        #pragma unroll
        for (int j = 0; j < 4; j++) {
            int row = wm * 64 + i * 16 + (lane >> 2);
            int col = wn * 32 + j * 8 + (lane & 3) * 2;
            *(float2*)&Csm[(size_t)row * 136 + col] =
                make_float2(acc[i][j][0], acc[i][j][1]);
            *(float2*)&Csm[(size_t)(row + 8) * 136 + col] =
                make_float2(acc[i][j][2], acc[i][j][3]);
        }
    __syncthreads();

    int r    = tid >> 1;
    int half = tid & 1;
    int m    = m0 + r;
    const float* csrc = Csm + (size_t)r * 136 + half * 64;

    if (mode == 0) {
        float* dst = outp + (size_t)m * 256 + n0 + half * 64;
        #pragma unroll
        for (int j = 0; j < 16; j++)
            *(float4*)(dst + 4 * j) = *(const float4*)(csrc + 4 * j);
    } else {
        int b = m / Tt, t = m % Tt;
        int g = (n0 >> 6) + half;   // 0..3 Q heads, 4..5 K kv, 6..7 V kv
        float vals[64];
        if (g < 6) {
            #pragma unroll
            for (int i = 0; i < 32; i++) {
                float cs = ctab[t * 32 + i], sn = stab[t * 32 + i];
                float x0 = csrc[i], x1 = csrc[32 + i];
                vals[i]      = x0 * cs - x1 * sn;
                vals[i + 32] = x1 * cs + x0 * sn;
            }
            if (g < 4) {
                #pragma unroll
                for (int i = 0; i < 64; i++) vals[i] *= 0.125f;   // 1/sqrt(D)
            }
        } else {
            #pragma unroll
            for (int i = 0; i < 64; i++) vals[i] = csrc[i];
        }
        uint32_t hw[32], lw[32];
        #pragma unroll
        for (int jj = 0; jj < 32; jj++)
            split_pack2(vals[2 * jj], vals[2 * jj + 1], hw[jj], lw[jj]);

        size_t idx;
        bf16 *dh, *dl;
        if (g < 4)      { idx = (((size_t)b * Hh  + g      ) * Tt + t) * 64; dh = qh; dl = ql; }
        else if (g < 6) { idx = (((size_t)b * KVh + (g - 4)) * Tt + t) * 64; dh = kh; dl = kl; }
        else            { idx = (((size_t)b * KVh + (g - 6)) * Tt + t) * 64; dh = vh; dl = vl; }
        uint4* dh4 = (uint4*)(dh + idx);
        uint4* dl4 = (uint4*)(dl + idx);
        #pragma unroll
        for (int u = 0; u < 8; u++) {
            dh4[u] = make_uint4(hw[4*u], hw[4*u+1], hw[4*u+2], hw[4*u+3]);
            dl4[u] = make_uint4(lw[4*u], lw[4*u+1], lw[4*u+2], lw[4*u+3]);
        }
    }
}

// ===================== HMMA causal GQA flash attention (occ-2, 1 sync/tile) ==
// grid (T/128, H, B), 256 threads. Warp w owns q rows [w*16, w*16+16).
// smem (80KB, 2 CTAs/SM): Qlo 16KB | KV stage0 32KB | KV stage1 32KB.
// Q-hi staged through stage1 (transient), fragments in regs.
// Loop: wait0 -> sync -> issue(kt+1) -> compute(kt)  (ONE sync per tile).
__global__ __launch_bounds__(256, 2)
void attn_mma_kernel(const bf16* __restrict__ qh, const bf16* __restrict__ ql,
                     const bf16* __restrict__ kh, const bf16* __restrict__ kl,
                     const bf16* __restrict__ vh, const bf16* __restrict__ vl,
                     bf16* __restrict__ yh, bf16* __restrict__ yl)
{
    extern __shared__ char smem[];
    uint32_t ub  = smem_to_u32(smem);
    uint32_t uQl = ub;                       // 16KB persistent Q-lo

    int tid  = threadIdx.x;
    int w    = tid >> 5, lane = tid & 31;
    int q0   = blockIdx.x * 128;
    int h    = blockIdx.y;
    int b    = blockIdx.z;
    int kvh  = h >> 1;

    size_t kvbase = ((size_t)b * KVh + kvh) * Tt * 64;
    int ntiles = q0 / 64 + 2;

    // cp.async KV mapping: 4 threads per row
    int krow = tid >> 2, part = tid & 3;
    const bf16* gK0 = kh + kvbase + (size_t)krow * 64 + part * 16;
    const bf16* gK1 = kl + kvbase + (size_t)krow * 64 + part * 16;
    const bf16* gV0 = vh + kvbase + (size_t)krow * 64 + part * 16;
    const bf16* gV1 = vl + kvbase + (size_t)krow * 64 + part * 16;
    uint32_t d0 = swz(krow, part * 32);
    uint32_t d1 = swz(krow, part * 32 + 16);

    auto issueKV = [&](int kt, int s) {
        uint32_t base = ub + 16384 + (uint32_t)s * 32768;
        size_t off = (size_t)kt * 4096;
        CP16(base         + d0, gK0 + off); CP16(base         + d1, gK0 + off + 8);
        CP16(base +  8192 + d0, gK1 + off); CP16(base +  8192 + d1, gK1 + off + 8);
        CP16(base + 16384 + d0, gV0 + off); CP16(base + 16384 + d1, gV0 + off + 8);
        CP16(base + 24576 + d0, gV1 + off); CP16(base + 24576 + d1, gV1 + off + 8);
        CP_COMMIT();
    };

    // ---- stage Q: hi -> stage1 region (transient), lo -> persistent uQl ----
    {
        int row = tid >> 1, hf2 = tid & 1;
        size_t src = (((size_t)b * Hh + h) * Tt + q0 + row) * 64 + hf2 * 32;
        const uint4* s0 = (const uint4*)(qh + src);
        const uint4* s1 = (const uint4*)(ql + src);
        #pragma unroll
        for (int j = 0; j < 4; j++) {
            uint32_t off = swz(row, hf2 * 64 + j * 16);
            *(uint4*)(smem + 16384 + 32768 + off) = s0[j];   // Q-hi in stage1
            *(uint4*)(smem + off)                 = s1[j];   // Q-lo persistent
        }
    }
    issueKV(0, 0);     // prefetch KV tile 0 into stage0
    __syncthreads();

    // ---- Q-hi fragments (persist in regs); then release stage1 ----
    int qar = w * 16 + (lane & 15);
    int qac_base = ((lane >> 4) << 3) * 2;
    uint32_t qfh[4][4];
    #pragma unroll
    for (int ks = 0; ks < 4; ks++)
        LDSM_X4(qfh[ks][0], qfh[ks][1], qfh[ks][2], qfh[ks][3],
                ub + 16384 + 32768 + swz(qar, ks * 32 + qac_base));
    __syncthreads();   // all warps done reading Q-hi before tile1 overwrites

    float o[8][4];
    #pragma unroll
    for (int i = 0; i < 8; i++)
        #pragma unroll
        for (int e = 0; e < 4; e++) o[i][e] = 0.f;
    float m0v = -1e30f, m1v = -1e30f, l0v = 0.f, l1v = 0.f;

    int warp_max_row = q0 + w * 16 + 15;

    #pragma unroll 1
    for (int kt = 0; kt < ntiles; kt++) {
        CP_WAIT0();
        __syncthreads();   // stage (kt+1)&1 free (compute(kt-1) done), tile kt ready
        if (kt + 1 < ntiles) issueKV(kt + 1, (kt + 1) & 1);

        if (kt * 64 <= warp_max_row) {
            uint32_t kb = ub + 16384 + (uint32_t)(kt & 1) * 32768;
            uint32_t uKh = kb, uKl = kb + 8192, uVh = kb + 16384, uVl = kb + 24576;

            // reload Q-lo fragments (per tile, keeps them out of the PV phase)
            uint32_t qfl[4][4];
            #pragma unroll
            for (int ks = 0; ks < 4; ks++)
                LDSM_X4(qfl[ks][0], qfl[ks][1], qfl[ks][2], qfl[ks][3],
                        uQl + swz(qar, ks * 32 + qac_base));

            // ---- S = Q @ K^T (bf16x3), K fragments streamed per-nf ----
            float s[8][4];
            #pragma unroll
            for (int j = 0; j < 8; j++)
                #pragma unroll
                for (int e = 0; e < 4; e++) s[j][e] = 0.f;

            int br = (lane & 7) + ((lane >> 4) << 3);
            #pragma unroll
            for (int ks = 0; ks < 4; ks++) {
                int bc = (ks * 16 + (((lane >> 3) & 1) << 3)) * 2;
                #pragma unroll
                for (int nf = 0; nf < 4; nf++) {
                    uint32_t kbh[4], kbl[4];
                    LDSM_X4(kbh[0], kbh[1], kbh[2], kbh[3],
                            uKh + swz(nf * 16 + br, bc));
                    LDSM_X4(kbl[0], kbl[1], kbl[2], kbl[3],
                            uKl + swz(nf * 16 + br, bc));
                    #pragma unroll
                    for (int p = 0; p < 2; p++) {
                        int j = nf * 2 + p;
                        MMA_BF16(s[j], qfh[ks], kbh[2*p], kbh[2*p+1]);
                        MMA_BF16(s[j], qfl[ks], kbh[2*p], kbh[2*p+1]);
                        MMA_BF16(s[j], qfh[ks], kbl[2*p], kbl[2*p+1]);
                    }
                }
            }

            // ---- causal mask ----
            int rowg = q0 + w * 16 + (lane >> 2);
            #pragma unroll
            for (int j = 0; j < 8; j++) {
                int colg = kt * 64 + j * 8 + 2 * (lane & 3);
                if (colg     > rowg)     s[j][0] = -1e30f;
                if (colg + 1 > rowg)     s[j][1] = -1e30f;
                if (colg     > rowg + 8) s[j][2] = -1e30f;
                if (colg + 1 > rowg + 8) s[j][3] = -1e30f;
            }

            // ---- online softmax (quad-shuffle row stats) ----
            float t0 = -1e30f, t1 = -1e30f;
            #pragma unroll
            for (int j = 0; j < 8; j++) {
                t0 = fmaxf(t0, fmaxf(s[j][0], s[j][1]));
                t1 = fmaxf(t1, fmaxf(s[j][2], s[j][3]));
            }
            t0 = fmaxf(t0, __shfl_xor_sync(0xffffffffu, t0, 1));
            t0 = fmaxf(t0, __shfl_xor_sync(0xffffffffu, t0, 2));
            t1 = fmaxf(t1, __shfl_xor_sync(0xffffffffu, t1, 1));
            t1 = fmaxf(t1, __shfl_xor_sync(0xffffffffu, t1, 2));
            float mn0 = fmaxf(m0v, t0), mn1 = fmaxf(m1v, t1);
            float f0 = __expf(m0v - mn0), f1 = __expf(m1v - mn1);
            m0v = mn0; m1v = mn1;

            float ps0 = 0.f, ps1 = 0.f;
            #pragma unroll
            for (int j = 0; j < 8; j++) {
                s[j][0] = __expf(s[j][0] - mn0); ps0 += s[j][0];
                s[j][1] = __expf(s[j][1] - mn0); ps0 += s[j][1];
                s[j][2] = __expf(s[j][2] - mn1); ps1 += s[j][2];
                s[j][3] = __expf(s[j][3] - mn1); ps1 += s[j][3];
            }
            ps0 += __shfl_xor_sync(0xffffffffu, ps0, 1);
            ps0 += __shfl_xor_sync(0xffffffffu, ps0, 2);
            ps1 += __shfl_xor_sync(0xffffffffu, ps1, 1);
            ps1 += __shfl_xor_sync(0xffffffffu, ps1, 2);
            l0v = l0v * f0 + ps0;
            l1v = l1v * f1 + ps1;

            #pragma unroll
            for (int dn = 0; dn < 8; dn++) {
                o[dn][0] *= f0; o[dn][1] *= f0;
                o[dn][2] *= f1; o[dn][3] *= f1;
            }

            // ---- P fragments (accumulator -> A-frag identity, hi/lo) ----
            uint32_t pah[4][4], pal[4][4];
            #pragma unroll
            for (int kc = 0; kc < 4; kc++) {
                split_pack2(s[2*kc][0],   s[2*kc][1],   pah[kc][0], pal[kc][0]);
                split_pack2(s[2*kc][2],   s[2*kc][3],   pah[kc][1], pal[kc][1]);
                split_pack2(s[2*kc+1][0], s[2*kc+1][1], pah[kc][2], pal[kc][2]);
                split_pack2(s[2*kc+1][2], s[2*kc+1][3], pah[kc][3], pal[kc][3]);
            }

            // ---- O += P @ V (bf16x3), V frags streamed via ldmatrix.trans ----
            #pragma unroll
            for (int kc = 0; kc < 4; kc++) {
                int vr = kc * 16 + (lane & 7) + ((lane >> 3) & 1) * 8;
                #pragma unroll
                for (int dn2 = 0; dn2 < 4; dn2++) {
                    int vc = (dn2 * 16 + (lane >> 4) * 8) * 2;
                    uint32_t vbh[4], vbl[4];
                    LDSM_X4_T(vbh[0], vbh[1], vbh[2], vbh[3], uVh + swz(vr, vc));
                    LDSM_X4_T(vbl[0], vbl[1], vbl[2], vbl[3], uVl + swz(vr, vc));
                    #pragma unroll
                    for (int p = 0; p < 2; p++) {
                        int dn = dn2 * 2 + p;
                        MMA_BF16(o[dn], pah[kc], vbh[2*p], vbh[2*p+1]);
                        MMA_BF16(o[dn], pal[kc], vbh[2*p], vbh[2*p+1]);
                        MMA_BF16(o[dn], pah[kc], vbl[2*p], vbl[2*p+1]);
                    }
                }
            }
        }
    }

    // ---- epilogue: y split bf16 hi/lo, layout [B,T,H*D] ----
    float i0 = 1.f / l0v, i1 = 1.f / l1v;
    int row0 = q0 + w * 16 + (lane >> 2);
    int colb = h * 64 + 2 * (lane & 3);
    #pragma unroll
    for (int dn = 0; dn < 8; dn++) {
        size_t off0 = ((size_t)b * Tt + row0) * 256 + colb + dn * 8;
        size_t off1 = ((size_t)b * Tt + row0 + 8) * 256 + colb + dn * 8;
        uint32_t hi, lo;
        split_pack2(o[dn][0] * i0, o[dn][1] * i0, hi, lo);
        *(uint32_t*)(yh + off0) = hi;
        *(uint32_t*)(yl + off0) = lo;
        split_pack2(o[dn][2] * i1, o[dn][3] * i1, hi, lo);
        *(uint32_t*)(yh + off1) = hi;
        *(uint32_t*)(yl + off1) = lo;
    }
}

// ===================== launcher ==============================================
extern "C" void kernel_launch(void* const* d_in, const int* in_sizes, int n_in,
                              void* d_out, int out_size)
{
    const float* x  = (const float*)d_in[0];
    const float* Wq = (const float*)d_in[1];
    const float* Wk = (const float*)d_in[2];
    const float* Wv = (const float*)d_in[3];
    const float* Wo = (const float*)d_in[4];
    float* out = (float*)d_out;

    float *cosp, *sinp;
    bf16 *xh, *xl, *yhp, *ylp;
    bf16 *wqh, *wql, *woh, *wol;
    bf16 *qhp, *qlp, *khp, *klp, *vhp, *vlp;
    cudaGetSymbolAddress((void**)&cosp, g_cos);
    cudaGetSymbolAddress((void**)&sinp, g_sin);
    cudaGetSymbolAddress((void**)&xh, g_xh);
    cudaGetSymbolAddress((void**)&xl, g_xl);
    cudaGetSymbolAddress((void**)&yhp, g_yh);
    cudaGetSymbolAddress((void**)&ylp, g_yl);
    cudaGetSymbolAddress((void**)&wqh, g_wqkv_hi);
    cudaGetSymbolAddress((void**)&wql, g_wqkv_lo);
    cudaGetSymbolAddress((void**)&woh, g_wo_hi);
    cudaGetSymbolAddress((void**)&wol, g_wo_lo);
    cudaGetSymbolAddress((void**)&qhp, g_qh);
    cudaGetSymbolAddress((void**)&qlp, g_ql);
    cudaGetSymbolAddress((void**)&khp, g_kh);
    cudaGetSymbolAddress((void**)&klp, g_kl);
    cudaGetSymbolAddress((void**)&vhp, g_vh);
    cudaGetSymbolAddress((void**)&vlp, g_vl);

    const int M = Bb * Tt;                 // 49152
    const int gemm_smem = 98304;           // 3 stages x 32K (C bounce fits inside)
    const int attn_smem = 81920;           // Qlo 16K + 2 KV stages 64K

    cudaFuncSetAttribute(gemm_mma_kernel,
                         cudaFuncAttributeMaxDynamicSharedMemorySize, gemm_smem);
    cudaFuncSetAttribute(attn_mma_kernel,
                         cudaFuncAttributeMaxDynamicSharedMemorySize, attn_smem);

    // 1. split x to bf16 hi/lo ; weight pack/split + rope tables
    split_x_kernel<<<12288, 256>>>((const float4*)x, (uint2*)xh, (uint2*)xl);
    prep_kernel<<<816, 256>>>(Wq, Wk, Wv, Wo);

    // 2. fused QKV projection + RoPE + split epilogue (Ntot = 512)
    gemm_mma_kernel<<<dim3(4, M / 128), 256, gemm_smem>>>(
        xh, xl, wqh, wql, nullptr,
        qhp, qlp, khp, klp, vhp, vlp, cosp, sinp, 1);

    // 3. HMMA flash attention (writes y split)
    attn_mma_kernel<<<dim3(Tt / 128, Hh, Bb), 256, attn_smem>>>(
        qhp, qlp, khp, klp, vhp, vlp, yhp, ylp);

    // 4. output projection (Ntot = 256)
    gemm_mma_kernel<<<dim3(2, M / 128), 256, gemm_smem>>>(
        yhp, ylp, woh, wol, out,
        nullptr, nullptr, nullptr, nullptr, nullptr, nullptr,
        nullptr, nullptr, 0);
}